// round 12
// baseline (speedup 1.0000x reference)
#include <cuda_runtime.h>
#include <math.h>

#define N_NODES 25000
#define N_EDGES 250000
#define DIM 64
#define HEADS 4
#define C 256            // HEADS*DIM
#define EB 16            // edges per tile (mma m16)
#define SQS 264          // sq row stride (floats): conflict-free STS
#define LOG2E 1.4426950408889634f
#define LN2   0.6931471805599453f

// dynamic smem partition (bytes)
#define SB_BYTES   32768                          // 8192 x uint (bf16-pair B frags)
#define SEA_OFF    SB_BYTES                       // [2][EB][68] unsigned = 8704
#define SQ_OFF     (SEA_OFF + 8704)               // [2][EB][SQS] float = 33792
#define SII_OFF    (SQ_OFF + 33792)               // [2][EB] int = 128
#define SJJ_OFF    (SII_OFF + 128)                // [2][EB] int = 128
#define SBN_OFF    (SJJ_OFF + 128)                // [2][HEADS] float = 32
#define SMEM_TOTAL (SBN_OFF + 32)

// Scratch
__device__ float g_P[N_NODES * C];                       // (x @ W_top) * log2e
__device__ __align__(16) float g_num[N_NODES * C];       // unnormalized aggregation (log2-domain oj)
__device__ float g_denom[N_NODES * HEADS];

__device__ __forceinline__ float ex2f(float x) {
    float r; asm("ex2.approx.f32 %0, %1;" : "=f"(r) : "f"(x)); return r;
}
__device__ __forceinline__ float lg2f(float x) {
    float r; asm("lg2.approx.f32 %0, %1;" : "=f"(r) : "f"(x)); return r;
}
// log2-domain softplus: input x already scaled by log2e; returns softplus(x/log2e)/ln2
__device__ __forceinline__ float l2sp(float x) { return lg2f(1.f + ex2f(x)); }

__device__ __forceinline__ unsigned tf32(float x) {
    float r;
    asm("cvt.rna.tf32.f32 %0, %1;" : "=f"(r) : "f"(x));
    return __float_as_uint(r);
}
// pack bf16(a) in high half, bf16(b) in low half
__device__ __forceinline__ unsigned pk_bf16(float a, float b) {
    unsigned r;
    asm("{.reg .b16 lo, hi; cvt.rn.bf16.f32 hi, %1; cvt.rn.bf16.f32 lo, %2; mov.b32 %0, {lo, hi};}"
        : "=r"(r) : "f"(a), "f"(b));
    return r;
}
__device__ __forceinline__ void mma_tf32(float* d, const unsigned* a, unsigned b0, unsigned b1) {
    asm("mma.sync.aligned.m16n8k8.row.col.f32.tf32.tf32.f32 "
        "{%0,%1,%2,%3}, {%4,%5,%6,%7}, {%8,%9}, {%0,%1,%2,%3};"
        : "+f"(d[0]), "+f"(d[1]), "+f"(d[2]), "+f"(d[3])
        : "r"(a[0]), "r"(a[1]), "r"(a[2]), "r"(a[3]), "r"(b0), "r"(b1));
}
__device__ __forceinline__ unsigned long long pk2(float a, float b) {
    unsigned long long r;
    asm("mov.b64 %0, {%1, %2};" : "=l"(r) : "f"(a), "f"(b));
    return r;
}
__device__ __forceinline__ void ffma2(unsigned long long& acc,
                                      unsigned long long a, unsigned long long b) {
    asm("fma.rn.f32x2 %0, %1, %2, %0;" : "+l"(acc) : "l"(a), "l"(b));
}
__device__ __forceinline__ float2 unpk2(unsigned long long v) {
    float2 f;
    asm("mov.b64 {%0, %1}, %2;" : "=f"(f.x), "=f"(f.y) : "l"(v));
    return f;
}
__device__ __forceinline__ float4 l2sp4(float4 p, float4 q) {
    return make_float4(l2sp(p.x + q.x), l2sp(p.y + q.y), l2sp(p.z + q.z), l2sp(p.w + q.w));
}
__device__ __forceinline__ float dot4acc(float acc, float4 o, float4 c) {
    return fmaf(o.x, c.x, fmaf(o.y, c.y, fmaf(o.z, c.z, fmaf(o.w, c.w, acc))));
}
__device__ __forceinline__ void red4(float* p, float4 v) {
    asm volatile("red.global.add.v4.f32 [%0], {%1, %2, %3, %4};"
                 :: "l"(p), "f"(v.x), "f"(v.y), "f"(v.z), "f"(v.w) : "memory");
}

// P'[n, t] = (sum_k x[n,k] * W[k, t]) * log2e   + fused zero-fill of g_num/g_denom
__global__ void __launch_bounds__(256, 2) k_P(const float* __restrict__ x,
                                              const float* __restrict__ W) {
    int t = threadIdx.x;
    // fused init (block-stride, no ordering hazard: disjoint buffers)
    for (int i = blockIdx.x * 256 + t; i < N_NODES * C / 4; i += gridDim.x * 256)
        ((float4*)g_num)[i] = make_float4(0.f, 0.f, 0.f, 0.f);
    for (int i = blockIdx.x * 256 + t; i < N_NODES * HEADS; i += gridDim.x * 256)
        g_denom[i] = 0.f;

    unsigned long long w2[DIM / 2];
#pragma unroll
    for (int k = 0; k < DIM / 2; k++) w2[k] = pk2(W[(2 * k) * C + t], W[(2 * k + 1) * C + t]);
    __shared__ float4 sx[DIM / 4];
    for (int n = blockIdx.x; n < N_NODES; n += gridDim.x) {
        __syncthreads();
        if (t < 16) sx[t] = ((const float4*)(x + n * DIM))[t];
        __syncthreads();
        unsigned long long a0 = 0ull, a1 = 0ull, a2 = 0ull, a3 = 0ull;
#pragma unroll
        for (int k4 = 0; k4 < 16; k4 += 2) {
            float4 e0 = sx[k4], e1 = sx[k4 + 1];
            ffma2(a0, pk2(e0.x, e0.y), w2[2 * k4]);
            ffma2(a1, pk2(e0.z, e0.w), w2[2 * k4 + 1]);
            ffma2(a2, pk2(e1.x, e1.y), w2[2 * k4 + 2]);
            ffma2(a3, pk2(e1.z, e1.w), w2[2 * k4 + 3]);
        }
        float2 f0 = unpk2(a0), f1 = unpk2(a1), f2 = unpk2(a2), f3 = unpk2(a3);
        g_P[n * C + t] = (((f0.x + f0.y) + (f1.x + f1.y)) + ((f2.x + f2.y) + (f3.x + f3.y))) * LOG2E;
    }
}

// Fused edge pass: MMA (log2e-scaled) -> smem redistribute -> coalesced log2-domain epilogue.
__global__ void __launch_bounds__(256, 3) k_edge(
    const float* __restrict__ edge_attr, const float* __restrict__ W,
    const float* __restrict__ att, const float* __restrict__ bn_g,
    const float* __restrict__ bn_b, const float* __restrict__ bn_m,
    const float* __restrict__ bn_v, const int* __restrict__ ei) {
    const int t = threadIdx.x;
    const int w = t >> 5, lane = t & 31;
    const int g = lane >> 2, tg = lane & 3;

    extern __shared__ __align__(16) char dyn[];
    unsigned* sBh = (unsigned*)dyn;                                  // [8192] bf16-pair (x log2e)
    unsigned (*sea)[EB][68]  = (unsigned(*)[EB][68])(dyn + SEA_OFF); // tf32 bits
    float    (*sq)[EB][SQS]  = (float(*)[EB][SQS])(dyn + SQ_OFF);
    int      (*sii)[EB]      = (int(*)[EB])(dyn + SII_OFF);
    int      (*sjj)[EB]      = (int(*)[EB])(dyn + SJJ_OFF);
    float    (*sbn)[HEADS]   = (float(*)[HEADS])(dyn + SBN_OFF);

    // Fill B fragments (weights pre-scaled by log2e)
#pragma unroll
    for (int it = 0; it < 32; it++) {
        const int idx = t + it * 256;
        const int chunk = idx >> 5, l = idx & 31;
        const int wv = chunk >> 5, nb = (chunk >> 3) & 3, ks = chunk & 7;
        const int gg = l >> 2, tt = l & 3;
        const int n  = wv * 32 + nb * 8 + gg;
        const int k0 = ks * 8 + tt;
        sBh[idx] = pk_bf16(LOG2E * W[(DIM + k0) * C + n], LOG2E * W[(DIM + k0 + 4) * C + n]);
    }
    if (t < HEADS) {
        float s = bn_g[t] * rsqrtf(bn_v[t] + 1e-5f);
        sbn[0][t] = s;                               // scale: unchanged (ln2*log2e = 1 folds)
        sbn[1][t] = (bn_b[t] - bn_m[t] * s) * LOG2E; // shift pre-scaled by log2e
    }

    // per-lane att coefficients (UNscaled: L-domain dot gives pa*log2e directly)
    const int ha = lane >> 4, hb = 2 + ha;
    const int da = (lane * 4) & 63;
    const float4 aia = *(const float4*)&att[ha * 128 + da];
    const float4 aja = *(const float4*)&att[ha * 128 + 64 + da];
    const float4 aib = *(const float4*)&att[hb * 128 + da];
    const float4 ajb = *(const float4*)&att[hb * 128 + 64 + da];

    const int* idx_i = ei;
    const int* idx_j = ei + N_EDGES;
    const int e_ld = t >> 4, q4_ld = t & 15;
    const int stride = gridDim.x * EB;

    // prologue: tile 0 -> buffer 0
    int base0 = blockIdx.x * EB;
    {
        const float4 v = *(const float4*)&edge_attr[(size_t)(base0 + e_ld) * DIM + q4_ld * 4];
        uint4 u = make_uint4(tf32(v.x), tf32(v.y), tf32(v.z), tf32(v.w));
        *(uint4*)&sea[0][e_ld][q4_ld * 4] = u;
        if (t < EB) sii[0][t] = idx_i[base0 + t];
        else if (t < 2 * EB) sjj[0][t - EB] = idx_j[base0 + t - EB];
    }
    __syncthreads();   // covers B-fill + sbn + tile 0

    const float sa_a = sbn[0][ha], sbL_a = sbn[1][ha];
    const float sa_b = sbn[0][hb], sbL_b = sbn[1][hb];
    const int e0 = 2 * w, e1 = 2 * w + 1;

    int cur = 0;
    for (int base = base0; base < N_EDGES; base += stride) {
        const int nbase = base + stride;
        const bool has = nbase < N_EDGES;
        float4 vnext;
        int ij_next = 0;
        if (has) {
            vnext = *(const float4*)&edge_attr[(size_t)(nbase + e_ld) * DIM + q4_ld * 4];
            if (t < EB) ij_next = idx_i[nbase + t];
            else if (t < 2 * EB) ij_next = idx_j[nbase + t - EB];
        }
        const int ni0 = sii[cur][e0], nj0 = sjj[cur][e0];
        const int ni1 = sii[cur][e1], nj1 = sjj[cur][e1];

        // ---- MMA: q'[16 edges, 32 cols] (already log2e-scaled via W) ----
        float D[4][4];
#pragma unroll
        for (int nb = 0; nb < 4; nb++)
#pragma unroll
            for (int r = 0; r < 4; r++) D[nb][r] = 0.f;
#pragma unroll
        for (int ks = 0; ks < 8; ks++) {
            unsigned a[4];
            a[0] = sea[cur][g][ks * 8 + tg];
            a[1] = sea[cur][g + 8][ks * 8 + tg];
            a[2] = sea[cur][g][ks * 8 + tg + 4];
            a[3] = sea[cur][g + 8][ks * 8 + tg + 4];
#pragma unroll
            for (int nb = 0; nb < 4; nb++) {
                const unsigned u = sBh[(w * 32 + nb * 8 + ks) * 32 + lane];
                mma_tf32(D[nb], a, u & 0xffff0000u, u << 16);
            }
        }

        // ---- redistribute q' to edge-major smem (conflict-free STS.64) ----
#pragma unroll
        for (int nb = 0; nb < 4; nb++) {
            const int c = w * 32 + nb * 8 + tg * 2;
            *(float2*)&sq[cur][g][c]     = make_float2(D[nb][0], D[nb][1]);
            *(float2*)&sq[cur][g + 8][c] = make_float2(D[nb][2], D[nb][3]);
        }

        // commit next tile into the other buffer
        if (has) {
            uint4 u = make_uint4(tf32(vnext.x), tf32(vnext.y), tf32(vnext.z), tf32(vnext.w));
            *(uint4*)&sea[cur ^ 1][e_ld][q4_ld * 4] = u;
            if (t < EB) sii[cur ^ 1][t] = ij_next;
            else if (t < 2 * EB) sjj[cur ^ 1][t - EB] = ij_next;
        }
        __syncthreads();   // single barrier per tile

        // ---- coalesced log2-domain epilogue: warp w owns edges e0, e1 ----
        const int l4 = lane * 4;
#pragma unroll
        for (int sub = 0; sub < 2; sub++) {
            const int e  = sub ? e1 : e0;
            const int ni = sub ? ni1 : ni0;
            const int nj = sub ? nj1 : nj0;

            const float4 qa = *(const float4*)&sq[cur][e][l4];
            const float4 qb = *(const float4*)&sq[cur][e][128 + l4];
            const float4 pia = *(const float4*)&g_P[ni * C + l4];
            const float4 pib = *(const float4*)&g_P[ni * C + 128 + l4];
            const float4 pja = *(const float4*)&g_P[nj * C + l4];
            const float4 pjb = *(const float4*)&g_P[nj * C + 128 + l4];

            // L = softplus/ln2 (3 instr per element)
            const float4 Lia = l2sp4(pia, qa), Lja = l2sp4(pja, qa);
            const float4 Lib = l2sp4(pib, qb), Ljb = l2sp4(pjb, qb);

            // pa = (true logit)*log2e  — exactly what the next lg2-softplus wants
            float pa = dot4acc(dot4acc(0.f, Lia, aia), Lja, aja);
            float pb = dot4acc(dot4acc(0.f, Lib, aib), Ljb, ajb);
#pragma unroll
            for (int off = 1; off < 16; off <<= 1) {
                pa += __shfl_xor_sync(0xffffffffu, pa, off);
                pb += __shfl_xor_sync(0xffffffffu, pb, off);
            }
            // exp(softplus(BN(softplus))) = 1 + ex2(La*sa + sb*log2e)
            const float exa = 1.f + ex2f(fmaf(l2sp(pa), sa_a, sbL_a));
            const float exb = 1.f + ex2f(fmaf(l2sp(pb), sa_b, sbL_b));
            if ((lane & 15) == 0) {
                atomicAdd(&g_denom[ni * HEADS + ha], exa);
                atomicAdd(&g_denom[ni * HEADS + hb], exb);
            }
            red4(&g_num[(size_t)ni * C + l4],
                 make_float4(Lja.x * exa, Lja.y * exa, Lja.z * exa, Lja.w * exa));
            red4(&g_num[(size_t)ni * C + 128 + l4],
                 make_float4(Ljb.x * exb, Ljb.y * exb, Ljb.z * exb, Ljb.w * exb));
        }
        cur ^= 1;
    }
}

// out[n] = bias + 0.25*ln2 * sum_h num[n,h]/denom[n,h]   (ln2 deferred from log2-domain oj)
__global__ void k_final(const float* __restrict__ bias, float* __restrict__ out) {
    int i = blockIdx.x * blockDim.x + threadIdx.x;   // N_NODES*16 quads
    if (i >= N_NODES * 16) return;
    int n = i >> 4, q = i & 15;
    float inv[HEADS];
#pragma unroll
    for (int hh = 0; hh < HEADS; hh++) {
        float dn = g_denom[n * HEADS + hh];
        inv[hh] = (dn > 0.f) ? (0.25f * LN2) / dn : 0.f;
    }
    float4 acc = make_float4(0.f, 0.f, 0.f, 0.f);
#pragma unroll
    for (int hh = 0; hh < HEADS; hh++) {
        float4 v = *(const float4*)&g_num[n * C + hh * DIM + q * 4];
        acc.x += v.x * inv[hh]; acc.y += v.y * inv[hh];
        acc.z += v.z * inv[hh]; acc.w += v.w * inv[hh];
    }
    float4 b = *(const float4*)&bias[q * 4];
    acc.x += b.x; acc.y += b.y; acc.z += b.z; acc.w += b.w;
    *(float4*)&out[n * DIM + q * 4] = acc;
}

extern "C" void kernel_launch(void* const* d_in, const int* in_sizes, int n_in,
                              void* d_out, int out_size) {
    const float* x         = (const float*)d_in[0];
    const float* edge_attr = (const float*)d_in[1];
    const float* W         = (const float*)d_in[2];
    const float* att       = (const float*)d_in[3];
    const float* bias      = (const float*)d_in[4];
    const float* bn_g      = (const float*)d_in[5];
    const float* bn_b      = (const float*)d_in[6];
    const float* bn_m      = (const float*)d_in[7];
    const float* bn_v      = (const float*)d_in[8];
    const int*   ei        = (const int*)d_in[9];
    float* out = (float*)d_out;

    cudaFuncSetAttribute(k_edge, cudaFuncAttributeMaxDynamicSharedMemorySize, SMEM_TOTAL);

    k_P<<<592, 256>>>(x, W);
    k_edge<<<444, 256, SMEM_TOTAL>>>(edge_attr, W, att, bn_g, bn_b, bn_m, bn_v, ei);
    k_final<<<(N_NODES * 16 + 255) / 256, 256>>>(bias, out);
}

// round 13
// speedup vs baseline: 1.5847x; 1.5847x over previous
#include <cuda_runtime.h>
#include <math.h>

#define N_NODES 25000
#define N_EDGES 250000
#define DIM 64
#define HEADS 4
#define C 256            // HEADS*DIM
#define EB 16            // edges per tile (mma m16)
#define SQS 264          // sq row stride (floats): conflict-free STS
#define NT 8             // nodes per k_P tile

// dynamic smem partition (bytes)
#define SB_BYTES   32768                          // 8192 x uint (bf16-pair B frags)
#define SEA_OFF    SB_BYTES                       // [2][EB][68] unsigned = 8704
#define SQ_OFF     (SEA_OFF + 8704)               // [2][EB][SQS] float = 33792
#define SII_OFF    (SQ_OFF + 33792)               // [2][EB] int = 128
#define SJJ_OFF    (SII_OFF + 128)                // [2][EB] int = 128
#define SBN_OFF    (SJJ_OFF + 128)                // [2][HEADS] float = 32
#define SMEM_TOTAL (SBN_OFF + 32)

// Scratch
__device__ float g_P[N_NODES * C];                       // x @ W_top (fp32 exact)
__device__ __align__(16) float g_num[N_NODES * C];       // unnormalized aggregation
__device__ float g_denom[N_NODES * HEADS];

// 5-instruction softplus, valid for |x| < ~80 (our range: |x|<~10)
__device__ __forceinline__ float sp5(float x) {
    float t, r;
    asm("ex2.approx.f32 %0, %1;" : "=f"(t) : "f"(x * 1.4426950408889634f));
    asm("lg2.approx.f32 %0, %1;" : "=f"(r) : "f"(1.f + t));
    return r * 0.6931471805599453f;
}
__device__ __forceinline__ unsigned tf32(float x) {
    float r;
    asm("cvt.rna.tf32.f32 %0, %1;" : "=f"(r) : "f"(x));
    return __float_as_uint(r);
}
// pack bf16(a) in high half, bf16(b) in low half
__device__ __forceinline__ unsigned pk_bf16(float a, float b) {
    unsigned r;
    asm("{.reg .b16 lo, hi; cvt.rn.bf16.f32 hi, %1; cvt.rn.bf16.f32 lo, %2; mov.b32 %0, {lo, hi};}"
        : "=r"(r) : "f"(a), "f"(b));
    return r;
}
__device__ __forceinline__ void mma_tf32(float* d, const unsigned* a, unsigned b0, unsigned b1) {
    asm("mma.sync.aligned.m16n8k8.row.col.f32.tf32.tf32.f32 "
        "{%0,%1,%2,%3}, {%4,%5,%6,%7}, {%8,%9}, {%0,%1,%2,%3};"
        : "+f"(d[0]), "+f"(d[1]), "+f"(d[2]), "+f"(d[3])
        : "r"(a[0]), "r"(a[1]), "r"(a[2]), "r"(a[3]), "r"(b0), "r"(b1));
}
__device__ __forceinline__ unsigned long long pk2(float a, float b) {
    unsigned long long r;
    asm("mov.b64 %0, {%1, %2};" : "=l"(r) : "f"(a), "f"(b));
    return r;
}
__device__ __forceinline__ void ffma2(unsigned long long& acc,
                                      unsigned long long a, unsigned long long b) {
    asm("fma.rn.f32x2 %0, %1, %2, %0;" : "+l"(acc) : "l"(a), "l"(b));
}
__device__ __forceinline__ float2 unpk2(unsigned long long v) {
    float2 f;
    asm("mov.b64 {%0, %1}, %2;" : "=f"(f.x), "=f"(f.y) : "l"(v));
    return f;
}
__device__ __forceinline__ float4 sp4(float4 p, float4 q) {
    return make_float4(sp5(p.x + q.x), sp5(p.y + q.y), sp5(p.z + q.z), sp5(p.w + q.w));
}
__device__ __forceinline__ float dot4acc(float acc, float4 o, float4 c) {
    return fmaf(o.x, c.x, fmaf(o.y, c.y, fmaf(o.z, c.z, fmaf(o.w, c.w, acc))));
}
__device__ __forceinline__ void red4(float* p, float4 v) {
    asm volatile("red.global.add.v4.f32 [%0], {%1, %2, %3, %4};"
                 :: "l"(p), "f"(v.x), "f"(v.y), "f"(v.z), "f"(v.w) : "memory");
}

__global__ void k_initA() {
    int i = blockIdx.x * blockDim.x + threadIdx.x;
    if (i < N_NODES * C / 4) ((float4*)g_num)[i] = make_float4(0.f, 0.f, 0.f, 0.f);
}
__global__ void k_initB() {
    int i = blockIdx.x * blockDim.x + threadIdx.x;
    if (i < N_NODES * HEADS) g_denom[i] = 0.f;
}

// P[n, t] = sum_k x[n,k] * W[k, t]  (exact fp32). 8-node tiles, 8 indep chains.
__global__ void __launch_bounds__(256, 2) k_P(const float* __restrict__ x,
                                              const float* __restrict__ W) {
    const int t = threadIdx.x;
    unsigned long long w2[DIM / 2];
#pragma unroll
    for (int k = 0; k < DIM / 2; k++) w2[k] = pk2(W[(2 * k) * C + t], W[(2 * k + 1) * C + t]);
    __shared__ float4 sx[NT][DIM / 4];

    for (int nb = blockIdx.x * NT; nb < N_NODES; nb += gridDim.x * NT) {
        __syncthreads();
        if (t < NT * 16) {
            const int nn = t >> 4, q = t & 15;
            const int n = nb + nn;
            if (n < N_NODES) sx[nn][q] = ((const float4*)(x + (size_t)n * DIM))[q];
        }
        __syncthreads();

        unsigned long long acc[NT];
#pragma unroll
        for (int nn = 0; nn < NT; nn++) acc[nn] = 0ull;
#pragma unroll
        for (int q = 0; q < 16; q++) {
#pragma unroll
            for (int nn = 0; nn < NT; nn++) {      // 8 independent chains
                const float4 e = sx[nn][q];
                ffma2(acc[nn], pk2(e.x, e.y), w2[2 * q]);
                ffma2(acc[nn], pk2(e.z, e.w), w2[2 * q + 1]);
            }
        }
#pragma unroll
        for (int nn = 0; nn < NT; nn++) {
            const int n = nb + nn;
            if (n < N_NODES) {
                const float2 f = unpk2(acc[nn]);
                g_P[(size_t)n * C + t] = f.x + f.y;
            }
        }
    }
}

// Fused edge pass: MMA (fragment layout) -> smem redistribute -> coalesced epilogue.
__global__ void __launch_bounds__(256, 3) k_edge(
    const float* __restrict__ edge_attr, const float* __restrict__ W,
    const float* __restrict__ att, const float* __restrict__ bn_g,
    const float* __restrict__ bn_b, const float* __restrict__ bn_m,
    const float* __restrict__ bn_v, const int* __restrict__ ei) {
    const int t = threadIdx.x;
    const int w = t >> 5, lane = t & 31;
    const int g = lane >> 2, tg = lane & 3;

    extern __shared__ __align__(16) char dyn[];
    unsigned* sBh = (unsigned*)dyn;                                  // [8192] bf16-pair
    unsigned (*sea)[EB][68]  = (unsigned(*)[EB][68])(dyn + SEA_OFF); // tf32 bits
    float    (*sq)[EB][SQS]  = (float(*)[EB][SQS])(dyn + SQ_OFF);
    int      (*sii)[EB]      = (int(*)[EB])(dyn + SII_OFF);
    int      (*sjj)[EB]      = (int(*)[EB])(dyn + SJJ_OFF);
    float    (*sbn)[HEADS]   = (float(*)[HEADS])(dyn + SBN_OFF);

    // Fill B fragments: sBh[chunk*32 + lane], chunk = wv*32 + nb*8 + ks
#pragma unroll
    for (int it = 0; it < 32; it++) {
        const int idx = t + it * 256;
        const int chunk = idx >> 5, l = idx & 31;
        const int wv = chunk >> 5, nb = (chunk >> 3) & 3, ks = chunk & 7;
        const int gg = l >> 2, tt = l & 3;
        const int n  = wv * 32 + nb * 8 + gg;
        const int k0 = ks * 8 + tt;
        sBh[idx] = pk_bf16(W[(DIM + k0) * C + n], W[(DIM + k0 + 4) * C + n]);
    }
    if (t < HEADS) {
        float s = bn_g[t] * rsqrtf(bn_v[t] + 1e-5f);
        sbn[0][t] = s;
        sbn[1][t] = bn_b[t] - bn_m[t] * s;
    }

    // per-lane att coefficients for the coalesced epilogue
    const int ha = lane >> 4, hb = 2 + ha;          // head of col group a (0..127) / b (128..255)
    const int da = (lane * 4) & 63;
    const float4 aia = *(const float4*)&att[ha * 128 + da];
    const float4 aja = *(const float4*)&att[ha * 128 + 64 + da];
    const float4 aib = *(const float4*)&att[hb * 128 + da];
    const float4 ajb = *(const float4*)&att[hb * 128 + 64 + da];

    const int* idx_i = ei;
    const int* idx_j = ei + N_EDGES;
    const int e_ld = t >> 4, q4_ld = t & 15;
    const int stride = gridDim.x * EB;

    // prologue: tile 0 -> buffer 0
    int base0 = blockIdx.x * EB;
    {
        const float4 v = *(const float4*)&edge_attr[(size_t)(base0 + e_ld) * DIM + q4_ld * 4];
        uint4 u = make_uint4(tf32(v.x), tf32(v.y), tf32(v.z), tf32(v.w));
        *(uint4*)&sea[0][e_ld][q4_ld * 4] = u;
        if (t < EB) sii[0][t] = idx_i[base0 + t];
        else if (t < 2 * EB) sjj[0][t - EB] = idx_j[base0 + t - EB];
    }
    __syncthreads();   // covers B-fill + sbn + tile 0

    const float sa_a = sbn[0][ha], sb_a = sbn[1][ha];
    const float sa_b = sbn[0][hb], sb_b = sbn[1][hb];
    const int e0 = 2 * w, e1 = 2 * w + 1;

    int cur = 0;
    for (int base = base0; base < N_EDGES; base += stride) {
        const int nbase = base + stride;
        const bool has = nbase < N_EDGES;
        float4 vnext;
        int ij_next = 0;
        if (has) {
            vnext = *(const float4*)&edge_attr[(size_t)(nbase + e_ld) * DIM + q4_ld * 4];
            if (t < EB) ij_next = idx_i[nbase + t];
            else if (t < 2 * EB) ij_next = idx_j[nbase + t - EB];
        }
        // pre-read this warp's edge indices (sii[cur] stable until next iteration)
        const int ni0 = sii[cur][e0], nj0 = sjj[cur][e0];
        const int ni1 = sii[cur][e1], nj1 = sjj[cur][e1];

        // ---- MMA: q[16 edges, 32 cols] in fragment layout ----
        float D[4][4];
#pragma unroll
        for (int nb = 0; nb < 4; nb++)
#pragma unroll
            for (int r = 0; r < 4; r++) D[nb][r] = 0.f;
#pragma unroll
        for (int ks = 0; ks < 8; ks++) {
            unsigned a[4];
            a[0] = sea[cur][g][ks * 8 + tg];
            a[1] = sea[cur][g + 8][ks * 8 + tg];
            a[2] = sea[cur][g][ks * 8 + tg + 4];
            a[3] = sea[cur][g + 8][ks * 8 + tg + 4];
#pragma unroll
            for (int nb = 0; nb < 4; nb++) {
                const unsigned u = sBh[(w * 32 + nb * 8 + ks) * 32 + lane];
                mma_tf32(D[nb], a, u & 0xffff0000u, u << 16);
            }
        }

        // ---- redistribute q to edge-major smem (conflict-free STS.64) ----
#pragma unroll
        for (int nb = 0; nb < 4; nb++) {
            const int c = w * 32 + nb * 8 + tg * 2;
            *(float2*)&sq[cur][g][c]     = make_float2(D[nb][0], D[nb][1]);
            *(float2*)&sq[cur][g + 8][c] = make_float2(D[nb][2], D[nb][3]);
        }

        // commit next tile into the other buffer
        if (has) {
            uint4 u = make_uint4(tf32(vnext.x), tf32(vnext.y), tf32(vnext.z), tf32(vnext.w));
            *(uint4*)&sea[cur ^ 1][e_ld][q4_ld * 4] = u;
            if (t < EB) sii[cur ^ 1][t] = ij_next;
            else if (t < 2 * EB) sjj[cur ^ 1][t - EB] = ij_next;
        }
        __syncthreads();   // single barrier per tile

        // ---- coalesced epilogue: warp w owns edges e0, e1 (full 256-col rows) ----
        const int l4 = lane * 4;
#pragma unroll
        for (int sub = 0; sub < 2; sub++) {
            const int e  = sub ? e1 : e0;
            const int ni = sub ? ni1 : ni0;
            const int nj = sub ? nj1 : nj0;

            const float4 qa = *(const float4*)&sq[cur][e][l4];
            const float4 qb = *(const float4*)&sq[cur][e][128 + l4];
            const float4 pia = *(const float4*)&g_P[ni * C + l4];
            const float4 pib = *(const float4*)&g_P[ni * C + 128 + l4];
            const float4 pja = *(const float4*)&g_P[nj * C + l4];
            const float4 pjb = *(const float4*)&g_P[nj * C + 128 + l4];

            const float4 oia = sp4(pia, qa), oja = sp4(pja, qa);
            const float4 oib = sp4(pib, qb), ojb = sp4(pjb, qb);

            float pa = dot4acc(dot4acc(0.f, oia, aia), oja, aja);
            float pb = dot4acc(dot4acc(0.f, oib, aib), ojb, ajb);
#pragma unroll
            for (int off = 1; off < 16; off <<= 1) {
                pa += __shfl_xor_sync(0xffffffffu, pa, off);
                pb += __shfl_xor_sync(0xffffffffu, pb, off);
            }
            // per-16-lane-group: pa = logit sum for head ha, pb for head hb
            const float exa = __expf(sp5(fmaf(sp5(pa), sa_a, sb_a)));
            const float exb = __expf(sp5(fmaf(sp5(pb), sa_b, sb_b)));
            if ((lane & 15) == 0) {
                atomicAdd(&g_denom[ni * HEADS + ha], exa);
                atomicAdd(&g_denom[ni * HEADS + hb], exb);
            }
            red4(&g_num[(size_t)ni * C + l4],
                 make_float4(oja.x * exa, oja.y * exa, oja.z * exa, oja.w * exa));
            red4(&g_num[(size_t)ni * C + 128 + l4],
                 make_float4(ojb.x * exb, ojb.y * exb, ojb.z * exb, ojb.w * exb));
        }
        cur ^= 1;
    }
}

// out[n, q4] = bias + 0.25 * sum_h num[n,h,q4] / denom[n,h]
__global__ void k_final(const float* __restrict__ bias, float* __restrict__ out) {
    int i = blockIdx.x * blockDim.x + threadIdx.x;   // N_NODES*16 quads
    if (i >= N_NODES * 16) return;
    int n = i >> 4, q = i & 15;
    float inv[HEADS];
#pragma unroll
    for (int hh = 0; hh < HEADS; hh++) {
        float dn = g_denom[n * HEADS + hh];
        inv[hh] = (dn > 0.f) ? 0.25f / dn : 0.f;
    }
    float4 acc = make_float4(0.f, 0.f, 0.f, 0.f);
#pragma unroll
    for (int hh = 0; hh < HEADS; hh++) {
        float4 v = *(const float4*)&g_num[n * C + hh * DIM + q * 4];
        acc.x += v.x * inv[hh]; acc.y += v.y * inv[hh];
        acc.z += v.z * inv[hh]; acc.w += v.w * inv[hh];
    }
    float4 b = *(const float4*)&bias[q * 4];
    acc.x += b.x; acc.y += b.y; acc.z += b.z; acc.w += b.w;
    *(float4*)&out[n * DIM + q * 4] = acc;
}

extern "C" void kernel_launch(void* const* d_in, const int* in_sizes, int n_in,
                              void* d_out, int out_size) {
    const float* x         = (const float*)d_in[0];
    const float* edge_attr = (const float*)d_in[1];
    const float* W         = (const float*)d_in[2];
    const float* att       = (const float*)d_in[3];
    const float* bias      = (const float*)d_in[4];
    const float* bn_g      = (const float*)d_in[5];
    const float* bn_b      = (const float*)d_in[6];
    const float* bn_m      = (const float*)d_in[7];
    const float* bn_v      = (const float*)d_in[8];
    const int*   ei        = (const int*)d_in[9];
    float* out = (float*)d_out;

    cudaFuncSetAttribute(k_edge, cudaFuncAttributeMaxDynamicSharedMemorySize, SMEM_TOTAL);

    k_initA<<<(N_NODES * C / 4 + 255) / 256, 256>>>();
    k_initB<<<(N_NODES * HEADS + 255) / 256, 256>>>();
    k_P<<<592, 256>>>(x, W);
    k_edge<<<444, 256, SMEM_TOTAL>>>(edge_attr, W, att, bn_g, bn_b, bn_m, bn_v, ei);
    k_final<<<(N_NODES * 16 + 255) / 256, 256>>>(bias, out);
}

// round 14
// speedup vs baseline: 1.5921x; 1.0047x over previous
#include <cuda_runtime.h>
#include <math.h>

#define N_NODES 25000
#define N_EDGES 250000
#define DIM 64
#define HEADS 4
#define C 256            // HEADS*DIM
#define EB 16            // edges per tile (mma m16)
#define SQS 264          // sq row stride (floats): conflict-free STS
#define NT 8             // nodes per k_P tile
#define LOG2E 1.4426950408889634f
#define LN2   0.6931471805599453f

// dynamic smem partition (bytes)
#define SB_BYTES   32768                          // 8192 x uint (bf16-pair B frags)
#define SEA_OFF    SB_BYTES                       // [2][EB][68] unsigned = 8704
#define SQ_OFF     (SEA_OFF + 8704)               // [2][EB][SQS] float = 33792
#define SII_OFF    (SQ_OFF + 33792)               // [2][EB] int = 128
#define SJJ_OFF    (SII_OFF + 128)                // [2][EB] int = 128
#define SBN_OFF    (SJJ_OFF + 128)                // [2][HEADS] float = 32
#define SMEM_TOTAL (SBN_OFF + 32)

// Scratch
__device__ float g_P[N_NODES * C];                       // (x @ W_top) * log2e
__device__ __align__(16) float g_num[N_NODES * C];       // unnormalized aggregation (log2-domain)
__device__ float g_denom[N_NODES * HEADS];

__device__ __forceinline__ float ex2f(float x) {
    float r; asm("ex2.approx.f32 %0, %1;" : "=f"(r) : "f"(x)); return r;
}
__device__ __forceinline__ float lg2f(float x) {
    float r; asm("lg2.approx.f32 %0, %1;" : "=f"(r) : "f"(x)); return r;
}
// log2-domain softplus: arg pre-scaled by log2e; returns softplus(arg/log2e)/ln2
__device__ __forceinline__ float l2sp(float x) { return lg2f(1.f + ex2f(x)); }

__device__ __forceinline__ unsigned tf32(float x) {
    float r;
    asm("cvt.rna.tf32.f32 %0, %1;" : "=f"(r) : "f"(x));
    return __float_as_uint(r);
}
// pack bf16(a) in high half, bf16(b) in low half
__device__ __forceinline__ unsigned pk_bf16(float a, float b) {
    unsigned r;
    asm("{.reg .b16 lo, hi; cvt.rn.bf16.f32 hi, %1; cvt.rn.bf16.f32 lo, %2; mov.b32 %0, {lo, hi};}"
        : "=r"(r) : "f"(a), "f"(b));
    return r;
}
__device__ __forceinline__ void mma_tf32(float* d, const unsigned* a, unsigned b0, unsigned b1) {
    asm("mma.sync.aligned.m16n8k8.row.col.f32.tf32.tf32.f32 "
        "{%0,%1,%2,%3}, {%4,%5,%6,%7}, {%8,%9}, {%0,%1,%2,%3};"
        : "+f"(d[0]), "+f"(d[1]), "+f"(d[2]), "+f"(d[3])
        : "r"(a[0]), "r"(a[1]), "r"(a[2]), "r"(a[3]), "r"(b0), "r"(b1));
}
__device__ __forceinline__ unsigned long long pk2(float a, float b) {
    unsigned long long r;
    asm("mov.b64 %0, {%1, %2};" : "=l"(r) : "f"(a), "f"(b));
    return r;
}
__device__ __forceinline__ void ffma2(unsigned long long& acc,
                                      unsigned long long a, unsigned long long b) {
    asm("fma.rn.f32x2 %0, %1, %2, %0;" : "+l"(acc) : "l"(a), "l"(b));
}
__device__ __forceinline__ float2 unpk2(unsigned long long v) {
    float2 f;
    asm("mov.b64 {%0, %1}, %2;" : "=f"(f.x), "=f"(f.y) : "l"(v));
    return f;
}
__device__ __forceinline__ float4 l2sp4(float4 p, float4 q) {
    return make_float4(l2sp(p.x + q.x), l2sp(p.y + q.y), l2sp(p.z + q.z), l2sp(p.w + q.w));
}
__device__ __forceinline__ float dot4acc(float acc, float4 o, float4 c) {
    return fmaf(o.x, c.x, fmaf(o.y, c.y, fmaf(o.z, c.z, fmaf(o.w, c.w, acc))));
}
__device__ __forceinline__ void red4(float* p, float4 v) {
    asm volatile("red.global.add.v4.f32 [%0], {%1, %2, %3, %4};"
                 :: "l"(p), "f"(v.x), "f"(v.y), "f"(v.z), "f"(v.w) : "memory");
}

__global__ void k_initA() {
    int i = blockIdx.x * blockDim.x + threadIdx.x;
    if (i < N_NODES * C / 4) ((float4*)g_num)[i] = make_float4(0.f, 0.f, 0.f, 0.f);
}
__global__ void k_initB() {
    int i = blockIdx.x * blockDim.x + threadIdx.x;
    if (i < N_NODES * HEADS) g_denom[i] = 0.f;
}

// P'[n, t] = (sum_k x[n,k] * W[k, t]) * log2e. 8-node tiles, 8 indep chains.
__global__ void __launch_bounds__(256, 2) k_P(const float* __restrict__ x,
                                              const float* __restrict__ W) {
    const int t = threadIdx.x;
    unsigned long long w2[DIM / 2];
#pragma unroll
    for (int k = 0; k < DIM / 2; k++) w2[k] = pk2(W[(2 * k) * C + t], W[(2 * k + 1) * C + t]);
    __shared__ float4 sx[NT][DIM / 4];

    for (int nb = blockIdx.x * NT; nb < N_NODES; nb += gridDim.x * NT) {
        __syncthreads();
        if (t < NT * 16) {
            const int nn = t >> 4, q = t & 15;
            const int n = nb + nn;
            if (n < N_NODES) sx[nn][q] = ((const float4*)(x + (size_t)n * DIM))[q];
        }
        __syncthreads();

        unsigned long long acc[NT];
#pragma unroll
        for (int nn = 0; nn < NT; nn++) acc[nn] = 0ull;
#pragma unroll
        for (int q = 0; q < 16; q++) {
#pragma unroll
            for (int nn = 0; nn < NT; nn++) {      // 8 independent chains
                const float4 e = sx[nn][q];
                ffma2(acc[nn], pk2(e.x, e.y), w2[2 * q]);
                ffma2(acc[nn], pk2(e.z, e.w), w2[2 * q + 1]);
            }
        }
#pragma unroll
        for (int nn = 0; nn < NT; nn++) {
            const int n = nb + nn;
            if (n < N_NODES) {
                const float2 f = unpk2(acc[nn]);
                g_P[(size_t)n * C + t] = (f.x + f.y) * LOG2E;
            }
        }
    }
}

// Fused edge pass: MMA (log2e-folded) -> smem redistribute -> coalesced log2 epilogue.
__global__ void __launch_bounds__(256, 3) k_edge(
    const float* __restrict__ edge_attr, const float* __restrict__ W,
    const float* __restrict__ att, const float* __restrict__ bn_g,
    const float* __restrict__ bn_b, const float* __restrict__ bn_m,
    const float* __restrict__ bn_v, const int* __restrict__ ei) {
    const int t = threadIdx.x;
    const int w = t >> 5, lane = t & 31;
    const int g = lane >> 2, tg = lane & 3;

    extern __shared__ __align__(16) char dyn[];
    unsigned* sBh = (unsigned*)dyn;                                  // [8192] bf16(log2e*W)
    unsigned (*sea)[EB][68]  = (unsigned(*)[EB][68])(dyn + SEA_OFF); // tf32 bits
    float    (*sq)[EB][SQS]  = (float(*)[EB][SQS])(dyn + SQ_OFF);
    int      (*sii)[EB]      = (int(*)[EB])(dyn + SII_OFF);
    int      (*sjj)[EB]      = (int(*)[EB])(dyn + SJJ_OFF);
    float    (*sbn)[HEADS]   = (float(*)[HEADS])(dyn + SBN_OFF);

    // Fill B fragments (weights pre-scaled by log2e)
#pragma unroll
    for (int it = 0; it < 32; it++) {
        const int idx = t + it * 256;
        const int chunk = idx >> 5, l = idx & 31;
        const int wv = chunk >> 5, nb = (chunk >> 3) & 3, ks = chunk & 7;
        const int gg = l >> 2, tt = l & 3;
        const int n  = wv * 32 + nb * 8 + gg;
        const int k0 = ks * 8 + tt;
        sBh[idx] = pk_bf16(LOG2E * W[(DIM + k0) * C + n], LOG2E * W[(DIM + k0 + 4) * C + n]);
    }
    if (t < HEADS) {
        float s = bn_g[t] * rsqrtf(bn_v[t] + 1e-5f);
        sbn[0][t] = s;                               // scale: ln2*log2e = 1 folds exactly
        sbn[1][t] = (bn_b[t] - bn_m[t] * s) * LOG2E; // shift pre-scaled by log2e
    }

    // per-lane att coefficients (unscaled: L-domain dot yields logit*log2e directly)
    const int ha = lane >> 4, hb = 2 + ha;
    const int da = (lane * 4) & 63;
    const float4 aia = *(const float4*)&att[ha * 128 + da];
    const float4 aja = *(const float4*)&att[ha * 128 + 64 + da];
    const float4 aib = *(const float4*)&att[hb * 128 + da];
    const float4 ajb = *(const float4*)&att[hb * 128 + 64 + da];

    const int* idx_i = ei;
    const int* idx_j = ei + N_EDGES;
    const int e_ld = t >> 4, q4_ld = t & 15;
    const int stride = gridDim.x * EB;

    // prologue: tile 0 -> buffer 0
    int base0 = blockIdx.x * EB;
    {
        const float4 v = *(const float4*)&edge_attr[(size_t)(base0 + e_ld) * DIM + q4_ld * 4];
        uint4 u = make_uint4(tf32(v.x), tf32(v.y), tf32(v.z), tf32(v.w));
        *(uint4*)&sea[0][e_ld][q4_ld * 4] = u;
        if (t < EB) sii[0][t] = idx_i[base0 + t];
        else if (t < 2 * EB) sjj[0][t - EB] = idx_j[base0 + t - EB];
    }
    __syncthreads();   // covers B-fill + sbn + tile 0

    const float sa_a = sbn[0][ha], sbL_a = sbn[1][ha];
    const float sa_b = sbn[0][hb], sbL_b = sbn[1][hb];
    const int e0 = 2 * w, e1 = 2 * w + 1;

    int cur = 0;
    for (int base = base0; base < N_EDGES; base += stride) {
        const int nbase = base + stride;
        const bool has = nbase < N_EDGES;
        float4 vnext;
        int ij_next = 0;
        if (has) {
            vnext = *(const float4*)&edge_attr[(size_t)(nbase + e_ld) * DIM + q4_ld * 4];
            if (t < EB) ij_next = idx_i[nbase + t];
            else if (t < 2 * EB) ij_next = idx_j[nbase + t - EB];
        }
        const int ni0 = sii[cur][e0], nj0 = sjj[cur][e0];
        const int ni1 = sii[cur][e1], nj1 = sjj[cur][e1];

        // ---- MMA: q'[16 edges, 32 cols] (log2e folded via W) ----
        float D[4][4];
#pragma unroll
        for (int nb = 0; nb < 4; nb++)
#pragma unroll
            for (int r = 0; r < 4; r++) D[nb][r] = 0.f;
#pragma unroll
        for (int ks = 0; ks < 8; ks++) {
            unsigned a[4];
            a[0] = sea[cur][g][ks * 8 + tg];
            a[1] = sea[cur][g + 8][ks * 8 + tg];
            a[2] = sea[cur][g][ks * 8 + tg + 4];
            a[3] = sea[cur][g + 8][ks * 8 + tg + 4];
#pragma unroll
            for (int nb = 0; nb < 4; nb++) {
                const unsigned u = sBh[(w * 32 + nb * 8 + ks) * 32 + lane];
                mma_tf32(D[nb], a, u & 0xffff0000u, u << 16);
            }
        }

        // ---- redistribute q' to edge-major smem (conflict-free STS.64) ----
#pragma unroll
        for (int nb = 0; nb < 4; nb++) {
            const int c = w * 32 + nb * 8 + tg * 2;
            *(float2*)&sq[cur][g][c]     = make_float2(D[nb][0], D[nb][1]);
            *(float2*)&sq[cur][g + 8][c] = make_float2(D[nb][2], D[nb][3]);
        }

        // commit next tile into the other buffer
        if (has) {
            uint4 u = make_uint4(tf32(vnext.x), tf32(vnext.y), tf32(vnext.z), tf32(vnext.w));
            *(uint4*)&sea[cur ^ 1][e_ld][q4_ld * 4] = u;
            if (t < EB) sii[cur ^ 1][t] = ij_next;
            else if (t < 2 * EB) sjj[cur ^ 1][t - EB] = ij_next;
        }
        __syncthreads();   // single barrier per tile

        // ---- coalesced log2-domain epilogue: warp w owns edges e0, e1 ----
        const int l4 = lane * 4;
#pragma unroll
        for (int sub = 0; sub < 2; sub++) {
            const int e  = sub ? e1 : e0;
            const int ni = sub ? ni1 : ni0;
            const int nj = sub ? nj1 : nj0;

            const float4 qa = *(const float4*)&sq[cur][e][l4];
            const float4 qb = *(const float4*)&sq[cur][e][128 + l4];
            const float4 pia = *(const float4*)&g_P[ni * C + l4];
            const float4 pib = *(const float4*)&g_P[ni * C + 128 + l4];
            const float4 pja = *(const float4*)&g_P[nj * C + l4];
            const float4 pjb = *(const float4*)&g_P[nj * C + 128 + l4];

            // L = softplus/ln2 (3 instr per element)
            const float4 Lia = l2sp4(pia, qa), Lja = l2sp4(pja, qa);
            const float4 Lib = l2sp4(pib, qb), Ljb = l2sp4(pjb, qb);

            // pa = (true logit)*log2e — exactly what the lg2-softplus tail wants
            float pa = dot4acc(dot4acc(0.f, Lia, aia), Lja, aja);
            float pb = dot4acc(dot4acc(0.f, Lib, aib), Ljb, ajb);
#pragma unroll
            for (int off = 1; off < 16; off <<= 1) {
                pa += __shfl_xor_sync(0xffffffffu, pa, off);
                pb += __shfl_xor_sync(0xffffffffu, pb, off);
            }
            // exp(softplus(BN(softplus))) = 1 + 2^(L*sa + sb*log2e)  (exact identity)
            const float exa = 1.f + ex2f(fmaf(l2sp(pa), sa_a, sbL_a));
            const float exb = 1.f + ex2f(fmaf(l2sp(pb), sa_b, sbL_b));
            if ((lane & 15) == 0) {
                atomicAdd(&g_denom[ni * HEADS + ha], exa);
                atomicAdd(&g_denom[ni * HEADS + hb], exb);
            }
            red4(&g_num[(size_t)ni * C + l4],
                 make_float4(Lja.x * exa, Lja.y * exa, Lja.z * exa, Lja.w * exa));
            red4(&g_num[(size_t)ni * C + 128 + l4],
                 make_float4(Ljb.x * exb, Ljb.y * exb, Ljb.z * exb, Ljb.w * exb));
        }
        cur ^= 1;
    }
}

// out[n] = bias + 0.25*ln2 * sum_h num[n,h]/denom[n,h]   (ln2 deferred from log2 domain)
__global__ void k_final(const float* __restrict__ bias, float* __restrict__ out) {
    int i = blockIdx.x * blockDim.x + threadIdx.x;   // N_NODES*16 quads
    if (i >= N_NODES * 16) return;
    int n = i >> 4, q = i & 15;
    float inv[HEADS];
#pragma unroll
    for (int hh = 0; hh < HEADS; hh++) {
        float dn = g_denom[n * HEADS + hh];
        inv[hh] = (dn > 0.f) ? (0.25f * LN2) / dn : 0.f;
    }
    float4 acc = make_float4(0.f, 0.f, 0.f, 0.f);
#pragma unroll
    for (int hh = 0; hh < HEADS; hh++) {
        float4 v = *(const float4*)&g_num[n * C + hh * DIM + q * 4];
        acc.x += v.x * inv[hh]; acc.y += v.y * inv[hh];
        acc.z += v.z * inv[hh]; acc.w += v.w * inv[hh];
    }
    float4 b = *(const float4*)&bias[q * 4];
    acc.x += b.x; acc.y += b.y; acc.z += b.z; acc.w += b.w;
    *(float4*)&out[n * DIM + q * 4] = acc;
}

extern "C" void kernel_launch(void* const* d_in, const int* in_sizes, int n_in,
                              void* d_out, int out_size) {
    const float* x         = (const float*)d_in[0];
    const float* edge_attr = (const float*)d_in[1];
    const float* W         = (const float*)d_in[2];
    const float* att       = (const float*)d_in[3];
    const float* bias      = (const float*)d_in[4];
    const float* bn_g      = (const float*)d_in[5];
    const float* bn_b      = (const float*)d_in[6];
    const float* bn_m      = (const float*)d_in[7];
    const float* bn_v      = (const float*)d_in[8];
    const int*   ei        = (const int*)d_in[9];
    float* out = (float*)d_out;

    cudaFuncSetAttribute(k_edge, cudaFuncAttributeMaxDynamicSharedMemorySize, SMEM_TOTAL);

    k_initA<<<(N_NODES * C / 4 + 255) / 256, 256>>>();
    k_initB<<<(N_NODES * HEADS + 255) / 256, 256>>>();
    k_P<<<592, 256>>>(x, W);
    k_edge<<<444, 256, SMEM_TOTAL>>>(edge_attr, W, att, bn_g, bn_b, bn_m, bn_v, ei);
    k_final<<<(N_NODES * 16 + 255) / 256, 256>>>(bias, out);
}

// round 15
// speedup vs baseline: 1.8582x; 1.1671x over previous
#include <cuda_runtime.h>
#include <math.h>

#define N_NODES 25000
#define N_EDGES 250000
#define DIM 64
#define HEADS 4
#define C 256            // HEADS*DIM
#define EB 16            // edges per tile (mma m16)
#define SQS 264          // sq row stride (floats): conflict-free STS
#define SEAS 36          // sea row stride (uints, bf16 pairs): conflict-free frag loads
#define NT 8             // nodes per k_P tile
#define LOG2E 1.4426950408889634f
#define LN2   0.6931471805599453f

// dynamic smem partition (bytes)
#define SB_BYTES   32768                          // 4096 x uint2 (bf16-pair B frags, k16 layout)
#define SEA_OFF    SB_BYTES                       // [2][EB][SEAS] unsigned = 4608
#define SQ_OFF     (SEA_OFF + 4608)               // [2][EB][SQS] float = 33792
#define SII_OFF    (SQ_OFF + 33792)               // [2][EB] int = 128
#define SJJ_OFF    (SII_OFF + 128)                // [2][EB] int = 128
#define SBN_OFF    (SJJ_OFF + 128)                // [2][HEADS] float = 32
#define SMEM_TOTAL (SBN_OFF + 32)

// Scratch
__device__ float g_P[N_NODES * C];                       // (x @ W_top) * log2e
__device__ __align__(16) float g_num[N_NODES * C];       // unnormalized aggregation (log2-domain)
__device__ float g_denom[N_NODES * HEADS];

__device__ __forceinline__ float ex2f(float x) {
    float r; asm("ex2.approx.f32 %0, %1;" : "=f"(r) : "f"(x)); return r;
}
__device__ __forceinline__ float lg2f(float x) {
    float r; asm("lg2.approx.f32 %0, %1;" : "=f"(r) : "f"(x)); return r;
}
// log2-domain softplus: arg pre-scaled by log2e; returns softplus(arg/log2e)/ln2
__device__ __forceinline__ float l2sp(float x) { return lg2f(1.f + ex2f(x)); }

// pack bf16: lo = first (lower k), hi = second
__device__ __forceinline__ unsigned pk2bf16(float lo, float hi) {
    unsigned r;
    asm("{.reg .b16 l, h; cvt.rn.bf16.f32 l, %1; cvt.rn.bf16.f32 h, %2; mov.b32 %0, {l, h};}"
        : "=r"(r) : "f"(lo), "f"(hi));
    return r;
}
// m16n8k16 bf16 MMA: D += A x B
__device__ __forceinline__ void mma_bf16(float* d, const unsigned* a, unsigned b0, unsigned b1) {
    asm("mma.sync.aligned.m16n8k16.row.col.f32.bf16.bf16.f32 "
        "{%0,%1,%2,%3}, {%4,%5,%6,%7}, {%8,%9}, {%0,%1,%2,%3};"
        : "+f"(d[0]), "+f"(d[1]), "+f"(d[2]), "+f"(d[3])
        : "r"(a[0]), "r"(a[1]), "r"(a[2]), "r"(a[3]), "r"(b0), "r"(b1));
}
__device__ __forceinline__ unsigned long long pk2(float a, float b) {
    unsigned long long r;
    asm("mov.b64 %0, {%1, %2};" : "=l"(r) : "f"(a), "f"(b));
    return r;
}
__device__ __forceinline__ void ffma2(unsigned long long& acc,
                                      unsigned long long a, unsigned long long b) {
    asm("fma.rn.f32x2 %0, %1, %2, %0;" : "+l"(acc) : "l"(a), "l"(b));
}
__device__ __forceinline__ float2 unpk2(unsigned long long v) {
    float2 f;
    asm("mov.b64 {%0, %1}, %2;" : "=f"(f.x), "=f"(f.y) : "l"(v));
    return f;
}
__device__ __forceinline__ float4 l2sp4(float4 p, float4 q) {
    return make_float4(l2sp(p.x + q.x), l2sp(p.y + q.y), l2sp(p.z + q.z), l2sp(p.w + q.w));
}
__device__ __forceinline__ float dot4acc(float acc, float4 o, float4 c) {
    return fmaf(o.x, c.x, fmaf(o.y, c.y, fmaf(o.z, c.z, fmaf(o.w, c.w, acc))));
}
__device__ __forceinline__ void red4(float* p, float4 v) {
    asm volatile("red.global.add.v4.f32 [%0], {%1, %2, %3, %4};"
                 :: "l"(p), "f"(v.x), "f"(v.y), "f"(v.z), "f"(v.w) : "memory");
}

// single fused init launch
__global__ void k_init() {
    int i = blockIdx.x * blockDim.x + threadIdx.x;
    if (i < N_NODES * C / 4) ((float4*)g_num)[i] = make_float4(0.f, 0.f, 0.f, 0.f);
    if (i < N_NODES * HEADS) g_denom[i] = 0.f;
}

// P'[n, t] = (sum_k x[n,k] * W[k, t]) * log2e. 8-node tiles, 8 indep chains.
__global__ void __launch_bounds__(256, 2) k_P(const float* __restrict__ x,
                                              const float* __restrict__ W) {
    const int t = threadIdx.x;
    unsigned long long w2[DIM / 2];
#pragma unroll
    for (int k = 0; k < DIM / 2; k++) w2[k] = pk2(W[(2 * k) * C + t], W[(2 * k + 1) * C + t]);
    __shared__ float4 sx[NT][DIM / 4];

    for (int nb = blockIdx.x * NT; nb < N_NODES; nb += gridDim.x * NT) {
        __syncthreads();
        if (t < NT * 16) {
            const int nn = t >> 4, q = t & 15;
            const int n = nb + nn;
            if (n < N_NODES) sx[nn][q] = ((const float4*)(x + (size_t)n * DIM))[q];
        }
        __syncthreads();

        unsigned long long acc[NT];
#pragma unroll
        for (int nn = 0; nn < NT; nn++) acc[nn] = 0ull;
#pragma unroll
        for (int q = 0; q < 16; q++) {
#pragma unroll
            for (int nn = 0; nn < NT; nn++) {      // 8 independent chains
                const float4 e = sx[nn][q];
                ffma2(acc[nn], pk2(e.x, e.y), w2[2 * q]);
                ffma2(acc[nn], pk2(e.z, e.w), w2[2 * q + 1]);
            }
        }
#pragma unroll
        for (int nn = 0; nn < NT; nn++) {
            const int n = nb + nn;
            if (n < N_NODES) {
                const float2 f = unpk2(acc[nn]);
                g_P[(size_t)n * C + t] = (f.x + f.y) * LOG2E;
            }
        }
    }
}

// Fused edge pass: bf16 k16 MMA -> smem redistribute -> coalesced log2 epilogue.
__global__ void __launch_bounds__(256, 3) k_edge(
    const float* __restrict__ edge_attr, const float* __restrict__ W,
    const float* __restrict__ att, const float* __restrict__ bn_g,
    const float* __restrict__ bn_b, const float* __restrict__ bn_m,
    const float* __restrict__ bn_v, const int* __restrict__ ei) {
    const int t = threadIdx.x;
    const int w = t >> 5, lane = t & 31;
    const int g = lane >> 2, tg = lane & 3;

    extern __shared__ __align__(16) char dyn[];
    uint2*    sB2  = (uint2*)dyn;                                     // [4096] k16 B frags
    unsigned (*sea)[EB][SEAS] = (unsigned(*)[EB][SEAS])(dyn + SEA_OFF); // bf16-pair A
    float    (*sq)[EB][SQS]   = (float(*)[EB][SQS])(dyn + SQ_OFF);
    int      (*sii)[EB]       = (int(*)[EB])(dyn + SII_OFF);
    int      (*sjj)[EB]       = (int(*)[EB])(dyn + SJJ_OFF);
    float    (*sbn)[HEADS]    = (float(*)[HEADS])(dyn + SBN_OFF);

    // Fill B fragments (k16 layout, weights pre-scaled by log2e):
    // chunk = wv*16 + nb*4 + s ; lane (gg,tt): col n = wv*32+nb*8+gg
    //   .x = pairs k{16s+2tt, +1}, .y = pairs k{16s+8+2tt, +1}
#pragma unroll
    for (int it = 0; it < 16; it++) {
        const int idx = t + it * 256;
        const int chunk = idx >> 5, l = idx & 31;
        const int wv = chunk >> 4, nb = (chunk >> 2) & 3, s = chunk & 3;
        const int gg = l >> 2, tt = l & 3;
        const int n  = wv * 32 + nb * 8 + gg;
        const int k0 = s * 16 + 2 * tt;
        sB2[idx] = make_uint2(
            pk2bf16(LOG2E * W[(DIM + k0) * C + n],     LOG2E * W[(DIM + k0 + 1) * C + n]),
            pk2bf16(LOG2E * W[(DIM + k0 + 8) * C + n], LOG2E * W[(DIM + k0 + 9) * C + n]));
    }
    if (t < HEADS) {
        float s = bn_g[t] * rsqrtf(bn_v[t] + 1e-5f);
        sbn[0][t] = s;                               // scale: ln2*log2e = 1 folds exactly
        sbn[1][t] = (bn_b[t] - bn_m[t] * s) * LOG2E; // shift pre-scaled by log2e
    }

    // per-lane att coefficients (unscaled: L-domain dot yields logit*log2e directly)
    const int ha = lane >> 4, hb = 2 + ha;
    const int da = (lane * 4) & 63;
    const float4 aia = *(const float4*)&att[ha * 128 + da];
    const float4 aja = *(const float4*)&att[ha * 128 + 64 + da];
    const float4 aib = *(const float4*)&att[hb * 128 + da];
    const float4 ajb = *(const float4*)&att[hb * 128 + 64 + da];

    const int* idx_i = ei;
    const int* idx_j = ei + N_EDGES;
    const int e_ld = t >> 4, q4_ld = t & 15;
    const int stride = gridDim.x * EB;

    // prologue: tile 0 -> buffer 0 (A as bf16 pairs: uint2 per 4 floats)
    int base0 = blockIdx.x * EB;
    {
        const float4 v = *(const float4*)&edge_attr[(size_t)(base0 + e_ld) * DIM + q4_ld * 4];
        *(uint2*)&sea[0][e_ld][q4_ld * 2] =
            make_uint2(pk2bf16(v.x, v.y), pk2bf16(v.z, v.w));
        if (t < EB) sii[0][t] = idx_i[base0 + t];
        else if (t < 2 * EB) sjj[0][t - EB] = idx_j[base0 + t - EB];
    }
    __syncthreads();   // covers B-fill + sbn + tile 0

    const float sa_a = sbn[0][ha], sbL_a = sbn[1][ha];
    const float sa_b = sbn[0][hb], sbL_b = sbn[1][hb];
    const int e0 = 2 * w, e1 = 2 * w + 1;

    int cur = 0;
    for (int base = base0; base < N_EDGES; base += stride) {
        const int nbase = base + stride;
        const bool has = nbase < N_EDGES;
        float4 vnext;
        int ij_next = 0;
        if (has) {
            vnext = *(const float4*)&edge_attr[(size_t)(nbase + e_ld) * DIM + q4_ld * 4];
            if (t < EB) ij_next = idx_i[nbase + t];
            else if (t < 2 * EB) ij_next = idx_j[nbase + t - EB];
        }
        const int ni0 = sii[cur][e0], nj0 = sjj[cur][e0];
        const int ni1 = sii[cur][e1], nj1 = sjj[cur][e1];

        // ---- bf16 k16 MMA: q'[16 edges, 32 cols], 16 HMMA total ----
        float D[4][4];
#pragma unroll
        for (int nb = 0; nb < 4; nb++)
#pragma unroll
            for (int r = 0; r < 4; r++) D[nb][r] = 0.f;
#pragma unroll
        for (int s = 0; s < 4; s++) {
            unsigned a[4];
            a[0] = sea[cur][g][s * 8 + tg];          // row g,   k pair 16s+2tg
            a[1] = sea[cur][g + 8][s * 8 + tg];      // row g+8
            a[2] = sea[cur][g][s * 8 + 4 + tg];      // row g,   k pair 16s+8+2tg
            a[3] = sea[cur][g + 8][s * 8 + 4 + tg];  // row g+8
#pragma unroll
            for (int nb = 0; nb < 4; nb++) {
                const uint2 b = sB2[(w * 16 + nb * 4 + s) * 32 + lane];
                mma_bf16(D[nb], a, b.x, b.y);
            }
        }

        // ---- redistribute q' to edge-major smem (conflict-free STS.64) ----
#pragma unroll
        for (int nb = 0; nb < 4; nb++) {
            const int c = w * 32 + nb * 8 + tg * 2;
            *(float2*)&sq[cur][g][c]     = make_float2(D[nb][0], D[nb][1]);
            *(float2*)&sq[cur][g + 8][c] = make_float2(D[nb][2], D[nb][3]);
        }

        // commit next tile into the other buffer
        if (has) {
            *(uint2*)&sea[cur ^ 1][e_ld][q4_ld * 2] =
                make_uint2(pk2bf16(vnext.x, vnext.y), pk2bf16(vnext.z, vnext.w));
            if (t < EB) sii[cur ^ 1][t] = ij_next;
            else if (t < 2 * EB) sjj[cur ^ 1][t - EB] = ij_next;
        }
        __syncthreads();   // single barrier per tile

        // ---- coalesced log2-domain epilogue: warp w owns edges e0, e1 ----
        const int l4 = lane * 4;
#pragma unroll
        for (int sub = 0; sub < 2; sub++) {
            const int e  = sub ? e1 : e0;
            const int ni = sub ? ni1 : ni0;
            const int nj = sub ? nj1 : nj0;

            const float4 qa = *(const float4*)&sq[cur][e][l4];
            const float4 qb = *(const float4*)&sq[cur][e][128 + l4];
            const float4 pia = *(const float4*)&g_P[ni * C + l4];
            const float4 pib = *(const float4*)&g_P[ni * C + 128 + l4];
            const float4 pja = *(const float4*)&g_P[nj * C + l4];
            const float4 pjb = *(const float4*)&g_P[nj * C + 128 + l4];

            // L = softplus/ln2 (3 instr per element)
            const float4 Lia = l2sp4(pia, qa), Lja = l2sp4(pja, qa);
            const float4 Lib = l2sp4(pib, qb), Ljb = l2sp4(pjb, qb);

            // pa = (true logit)*log2e — exactly what the lg2-softplus tail wants
            float pa = dot4acc(dot4acc(0.f, Lia, aia), Lja, aja);
            float pb = dot4acc(dot4acc(0.f, Lib, aib), Ljb, ajb);
#pragma unroll
            for (int off = 1; off < 16; off <<= 1) {
                pa += __shfl_xor_sync(0xffffffffu, pa, off);
                pb += __shfl_xor_sync(0xffffffffu, pb, off);
            }
            // exp(softplus(BN(softplus))) = 1 + 2^(L*sa + sb*log2e)  (exact identity)
            const float exa = 1.f + ex2f(fmaf(l2sp(pa), sa_a, sbL_a));
            const float exb = 1.f + ex2f(fmaf(l2sp(pb), sa_b, sbL_b));
            if ((lane & 15) == 0) {
                atomicAdd(&g_denom[ni * HEADS + ha], exa);
                atomicAdd(&g_denom[ni * HEADS + hb], exb);
            }
            red4(&g_num[(size_t)ni * C + l4],
                 make_float4(Lja.x * exa, Lja.y * exa, Lja.z * exa, Lja.w * exa));
            red4(&g_num[(size_t)ni * C + 128 + l4],
                 make_float4(Ljb.x * exb, Ljb.y * exb, Ljb.z * exb, Ljb.w * exb));
        }
        cur ^= 1;
    }
}

// out[n] = bias + 0.25*ln2 * sum_h num[n,h]/denom[n,h]   (ln2 deferred from log2 domain)
__global__ void k_final(const float* __restrict__ bias, float* __restrict__ out) {
    int i = blockIdx.x * blockDim.x + threadIdx.x;   // N_NODES*16 quads
    if (i >= N_NODES * 16) return;
    int n = i >> 4, q = i & 15;
    float inv[HEADS];
#pragma unroll
    for (int hh = 0; hh < HEADS; hh++) {
        float dn = g_denom[n * HEADS + hh];
        inv[hh] = (dn > 0.f) ? (0.25f * LN2) / dn : 0.f;
    }
    float4 acc = make_float4(0.f, 0.f, 0.f, 0.f);
#pragma unroll
    for (int hh = 0; hh < HEADS; hh++) {
        float4 v = *(const float4*)&g_num[n * C + hh * DIM + q * 4];
        acc.x += v.x * inv[hh]; acc.y += v.y * inv[hh];
        acc.z += v.z * inv[hh]; acc.w += v.w * inv[hh];
    }
    float4 b = *(const float4*)&bias[q * 4];
    acc.x += b.x; acc.y += b.y; acc.z += b.z; acc.w += b.w;
    *(float4*)&out[n * DIM + q * 4] = acc;
}

extern "C" void kernel_launch(void* const* d_in, const int* in_sizes, int n_in,
                              void* d_out, int out_size) {
    const float* x         = (const float*)d_in[0];
    const float* edge_attr = (const float*)d_in[1];
    const float* W         = (const float*)d_in[2];
    const float* att       = (const float*)d_in[3];
    const float* bias      = (const float*)d_in[4];
    const float* bn_g      = (const float*)d_in[5];
    const float* bn_b      = (const float*)d_in[6];
    const float* bn_m      = (const float*)d_in[7];
    const float* bn_v      = (const float*)d_in[8];
    const int*   ei        = (const int*)d_in[9];
    float* out = (float*)d_out;

    cudaFuncSetAttribute(k_edge, cudaFuncAttributeMaxDynamicSharedMemorySize, SMEM_TOTAL);

    k_init<<<(N_NODES * C / 4 + 255) / 256, 256>>>();
    k_P<<<592, 256>>>(x, W);
    k_edge<<<444, 256, SMEM_TOTAL>>>(edge_attr, W, att, bn_g, bn_b, bn_m, bn_v, ei);
    k_final<<<(N_NODES * 16 + 255) / 256, 256>>>(bias, out);
}

// round 16
// speedup vs baseline: 1.9072x; 1.0264x over previous
#include <cuda_runtime.h>
#include <math.h>

#define N_NODES 25000
#define N_EDGES 250000
#define DIM 64
#define HEADS 4
#define C 256            // HEADS*DIM
#define EB 16            // edges per tile (mma m16)
#define SQH 132          // sq row stride (uints, bf16 pairs): conflict-free
#define SEAS 36          // sea row stride (uints, bf16 pairs): conflict-free frag loads
#define NT 8             // nodes per k_P tile
#define LOG2E 1.4426950408889634f
#define LN2   0.6931471805599453f

// dynamic smem partition (bytes)
#define SB_BYTES   32768                          // 4096 x uint2 (bf16-pair B frags, k16 layout)
#define SEA_OFF    SB_BYTES                       // [2][EB][SEAS] unsigned = 4608
#define SQ_OFF     (SEA_OFF + 4608)               // [2][EB][SQH] unsigned = 16896
#define SII_OFF    (SQ_OFF + 16896)               // [2][EB] int = 128
#define SJJ_OFF    (SII_OFF + 128)                // [2][EB] int = 128
#define SBN_OFF    (SJJ_OFF + 128)                // [2][HEADS] float = 32
#define SMEM_TOTAL (SBN_OFF + 32)                 // 54560 B -> 4 CTAs/SM

// Scratch
__device__ float g_P[N_NODES * C];                       // (x @ W_top) * log2e
__device__ __align__(16) float g_num[N_NODES * C];       // unnormalized aggregation (log2-domain)
__device__ float g_denom[N_NODES * HEADS];

__device__ __forceinline__ float ex2f(float x) {
    float r; asm("ex2.approx.f32 %0, %1;" : "=f"(r) : "f"(x)); return r;
}
__device__ __forceinline__ float lg2f(float x) {
    float r; asm("lg2.approx.f32 %0, %1;" : "=f"(r) : "f"(x)); return r;
}
// log2-domain softplus: arg pre-scaled by log2e; returns softplus(arg/log2e)/ln2
__device__ __forceinline__ float l2sp(float x) { return lg2f(1.f + ex2f(x)); }

// pack bf16: lo = first, hi = second
__device__ __forceinline__ unsigned pk2bf16(float lo, float hi) {
    unsigned r;
    asm("{.reg .b16 l, h; cvt.rn.bf16.f32 l, %1; cvt.rn.bf16.f32 h, %2; mov.b32 %0, {l, h};}"
        : "=r"(r) : "f"(lo), "f"(hi));
    return r;
}
// bf16 pair -> two floats (2 LOPs)
__device__ __forceinline__ float bf_lo(unsigned u) { return __uint_as_float(u << 16); }
__device__ __forceinline__ float bf_hi(unsigned u) { return __uint_as_float(u & 0xffff0000u); }

// m16n8k16 bf16 MMA: D += A x B
__device__ __forceinline__ void mma_bf16(float* d, const unsigned* a, unsigned b0, unsigned b1) {
    asm("mma.sync.aligned.m16n8k16.row.col.f32.bf16.bf16.f32 "
        "{%0,%1,%2,%3}, {%4,%5,%6,%7}, {%8,%9}, {%0,%1,%2,%3};"
        : "+f"(d[0]), "+f"(d[1]), "+f"(d[2]), "+f"(d[3])
        : "r"(a[0]), "r"(a[1]), "r"(a[2]), "r"(a[3]), "r"(b0), "r"(b1));
}
__device__ __forceinline__ unsigned long long pk2(float a, float b) {
    unsigned long long r;
    asm("mov.b64 %0, {%1, %2};" : "=l"(r) : "f"(a), "f"(b));
    return r;
}
__device__ __forceinline__ void ffma2(unsigned long long& acc,
                                      unsigned long long a, unsigned long long b) {
    asm("fma.rn.f32x2 %0, %1, %2, %0;" : "+l"(acc) : "l"(a), "l"(b));
}
__device__ __forceinline__ float2 unpk2(unsigned long long v) {
    float2 f;
    asm("mov.b64 {%0, %1}, %2;" : "=f"(f.x), "=f"(f.y) : "l"(v));
    return f;
}
__device__ __forceinline__ float4 l2sp4(float4 p, float4 q) {
    return make_float4(l2sp(p.x + q.x), l2sp(p.y + q.y), l2sp(p.z + q.z), l2sp(p.w + q.w));
}
__device__ __forceinline__ float dot4acc(float acc, float4 o, float4 c) {
    return fmaf(o.x, c.x, fmaf(o.y, c.y, fmaf(o.z, c.z, fmaf(o.w, c.w, acc))));
}
__device__ __forceinline__ void red4(float* p, float4 v) {
    asm volatile("red.global.add.v4.f32 [%0], {%1, %2, %3, %4};"
                 :: "l"(p), "f"(v.x), "f"(v.y), "f"(v.z), "f"(v.w) : "memory");
}

// single fused init launch
__global__ void k_init() {
    int i = blockIdx.x * blockDim.x + threadIdx.x;
    if (i < N_NODES * C / 4) ((float4*)g_num)[i] = make_float4(0.f, 0.f, 0.f, 0.f);
    if (i < N_NODES * HEADS) g_denom[i] = 0.f;
}

// P'[n, t] = (sum_k x[n,k] * W[k, t]) * log2e. 8-node tiles, 8 indep chains.
__global__ void __launch_bounds__(256, 2) k_P(const float* __restrict__ x,
                                              const float* __restrict__ W) {
    const int t = threadIdx.x;
    unsigned long long w2[DIM / 2];
#pragma unroll
    for (int k = 0; k < DIM / 2; k++) w2[k] = pk2(W[(2 * k) * C + t], W[(2 * k + 1) * C + t]);
    __shared__ float4 sx[NT][DIM / 4];

    for (int nb = blockIdx.x * NT; nb < N_NODES; nb += gridDim.x * NT) {
        __syncthreads();
        if (t < NT * 16) {
            const int nn = t >> 4, q = t & 15;
            const int n = nb + nn;
            if (n < N_NODES) sx[nn][q] = ((const float4*)(x + (size_t)n * DIM))[q];
        }
        __syncthreads();

        unsigned long long acc[NT];
#pragma unroll
        for (int nn = 0; nn < NT; nn++) acc[nn] = 0ull;
#pragma unroll
        for (int q = 0; q < 16; q++) {
#pragma unroll
            for (int nn = 0; nn < NT; nn++) {      // 8 independent chains
                const float4 e = sx[nn][q];
                ffma2(acc[nn], pk2(e.x, e.y), w2[2 * q]);
                ffma2(acc[nn], pk2(e.z, e.w), w2[2 * q + 1]);
            }
        }
#pragma unroll
        for (int nn = 0; nn < NT; nn++) {
            const int n = nb + nn;
            if (n < N_NODES) {
                const float2 f = unpk2(acc[nn]);
                g_P[(size_t)n * C + t] = (f.x + f.y) * LOG2E;
            }
        }
    }
}

// Fused edge pass: bf16 k16 MMA -> bf16 smem redistribute -> coalesced log2 epilogue.
__global__ void __launch_bounds__(256, 4) k_edge(
    const float* __restrict__ edge_attr, const float* __restrict__ W,
    const float* __restrict__ att, const float* __restrict__ bn_g,
    const float* __restrict__ bn_b, const float* __restrict__ bn_m,
    const float* __restrict__ bn_v, const int* __restrict__ ei) {
    const int t = threadIdx.x;
    const int w = t >> 5, lane = t & 31;
    const int g = lane >> 2, tg = lane & 3;

    extern __shared__ __align__(16) char dyn[];
    uint2*    sB2  = (uint2*)dyn;                                       // [4096] k16 B frags
    unsigned (*sea)[EB][SEAS] = (unsigned(*)[EB][SEAS])(dyn + SEA_OFF); // bf16-pair A
    unsigned (*sq)[EB][SQH]   = (unsigned(*)[EB][SQH])(dyn + SQ_OFF);   // bf16-pair q
    int      (*sii)[EB]       = (int(*)[EB])(dyn + SII_OFF);
    int      (*sjj)[EB]       = (int(*)[EB])(dyn + SJJ_OFF);
    float    (*sbn)[HEADS]    = (float(*)[HEADS])(dyn + SBN_OFF);

    // Fill B fragments (k16 layout, weights pre-scaled by log2e)
#pragma unroll
    for (int it = 0; it < 16; it++) {
        const int idx = t + it * 256;
        const int chunk = idx >> 5, l = idx & 31;
        const int wv = chunk >> 4, nb = (chunk >> 2) & 3, s = chunk & 3;
        const int gg = l >> 2, tt = l & 3;
        const int n  = wv * 32 + nb * 8 + gg;
        const int k0 = s * 16 + 2 * tt;
        sB2[idx] = make_uint2(
            pk2bf16(LOG2E * W[(DIM + k0) * C + n],     LOG2E * W[(DIM + k0 + 1) * C + n]),
            pk2bf16(LOG2E * W[(DIM + k0 + 8) * C + n], LOG2E * W[(DIM + k0 + 9) * C + n]));
    }
    if (t < HEADS) {
        float s = bn_g[t] * rsqrtf(bn_v[t] + 1e-5f);
        sbn[0][t] = s;                               // scale: ln2*log2e = 1 folds exactly
        sbn[1][t] = (bn_b[t] - bn_m[t] * s) * LOG2E; // shift pre-scaled by log2e
    }

    // per-lane att coefficients
    const int ha = lane >> 4, hb = 2 + ha;
    const int da = (lane * 4) & 63;
    const float4 aia = *(const float4*)&att[ha * 128 + da];
    const float4 aja = *(const float4*)&att[ha * 128 + 64 + da];
    const float4 aib = *(const float4*)&att[hb * 128 + da];
    const float4 ajb = *(const float4*)&att[hb * 128 + 64 + da];

    const int* idx_i = ei;
    const int* idx_j = ei + N_EDGES;
    const int e_ld = t >> 4, q4_ld = t & 15;
    const int stride = gridDim.x * EB;

    // prologue: tile 0 -> buffer 0
    int base0 = blockIdx.x * EB;
    {
        const float4 v = *(const float4*)&edge_attr[(size_t)(base0 + e_ld) * DIM + q4_ld * 4];
        *(uint2*)&sea[0][e_ld][q4_ld * 2] =
            make_uint2(pk2bf16(v.x, v.y), pk2bf16(v.z, v.w));
        if (t < EB) sii[0][t] = idx_i[base0 + t];
        else if (t < 2 * EB) sjj[0][t - EB] = idx_j[base0 + t - EB];
    }
    __syncthreads();   // covers B-fill + sbn + tile 0

    const float sa_a = sbn[0][ha], sbL_a = sbn[1][ha];
    const float sa_b = sbn[0][hb], sbL_b = sbn[1][hb];
    const int e0 = 2 * w, e1 = 2 * w + 1;

    int cur = 0;
    for (int base = base0; base < N_EDGES; base += stride) {
        const int nbase = base + stride;
        const bool has = nbase < N_EDGES;
        float4 vnext;
        int ij_next = 0;
        if (has) {
            vnext = *(const float4*)&edge_attr[(size_t)(nbase + e_ld) * DIM + q4_ld * 4];
            if (t < EB) ij_next = idx_i[nbase + t];
            else if (t < 2 * EB) ij_next = idx_j[nbase + t - EB];
        }
        const int ni0 = sii[cur][e0], nj0 = sjj[cur][e0];
        const int ni1 = sii[cur][e1], nj1 = sjj[cur][e1];

        // ---- bf16 k16 MMA: q'[16 edges, 32 cols], 16 HMMA total ----
        float D[4][4];
#pragma unroll
        for (int nb = 0; nb < 4; nb++)
#pragma unroll
            for (int r = 0; r < 4; r++) D[nb][r] = 0.f;
#pragma unroll
        for (int s = 0; s < 4; s++) {
            unsigned a[4];
            a[0] = sea[cur][g][s * 8 + tg];
            a[1] = sea[cur][g + 8][s * 8 + tg];
            a[2] = sea[cur][g][s * 8 + 4 + tg];
            a[3] = sea[cur][g + 8][s * 8 + 4 + tg];
#pragma unroll
            for (int nb = 0; nb < 4; nb++) {
                const uint2 b = sB2[(w * 16 + nb * 4 + s) * 32 + lane];
                mma_bf16(D[nb], a, b.x, b.y);
            }
        }

        // ---- redistribute q' as bf16 pairs (conflict-free STS.32: bank = lane+const) ----
#pragma unroll
        for (int nb = 0; nb < 4; nb++) {
            const int ci = w * 16 + nb * 4 + tg;          // uint col index (c/2)
            sq[cur][g][ci]     = pk2bf16(D[nb][0], D[nb][1]);
            sq[cur][g + 8][ci] = pk2bf16(D[nb][2], D[nb][3]);
        }

        // commit next tile into the other buffer
        if (has) {
            *(uint2*)&sea[cur ^ 1][e_ld][q4_ld * 2] =
                make_uint2(pk2bf16(vnext.x, vnext.y), pk2bf16(vnext.z, vnext.w));
            if (t < EB) sii[cur ^ 1][t] = ij_next;
            else if (t < 2 * EB) sjj[cur ^ 1][t - EB] = ij_next;
        }
        __syncthreads();   // single barrier per tile

        // ---- coalesced log2-domain epilogue: warp w owns edges e0, e1 ----
        const int l2i = lane * 2;            // uint index of col group a
#pragma unroll
        for (int sub = 0; sub < 2; sub++) {
            const int e  = sub ? e1 : e0;
            const int ni = sub ? ni1 : ni0;
            const int nj = sub ? nj1 : nj0;

            const uint2 ua = *(const uint2*)&sq[cur][e][l2i];
            const uint2 ub = *(const uint2*)&sq[cur][e][64 + l2i];
            const float4 qa = make_float4(bf_lo(ua.x), bf_hi(ua.x), bf_lo(ua.y), bf_hi(ua.y));
            const float4 qb = make_float4(bf_lo(ub.x), bf_hi(ub.x), bf_lo(ub.y), bf_hi(ub.y));
            const float4 pia = *(const float4*)&g_P[ni * C + lane * 4];
            const float4 pib = *(const float4*)&g_P[ni * C + 128 + lane * 4];
            const float4 pja = *(const float4*)&g_P[nj * C + lane * 4];
            const float4 pjb = *(const float4*)&g_P[nj * C + 128 + lane * 4];

            const float4 Lia = l2sp4(pia, qa), Lja = l2sp4(pja, qa);
            const float4 Lib = l2sp4(pib, qb), Ljb = l2sp4(pjb, qb);

            float pa = dot4acc(dot4acc(0.f, Lia, aia), Lja, aja);
            float pb = dot4acc(dot4acc(0.f, Lib, aib), Ljb, ajb);
#pragma unroll
            for (int off = 1; off < 16; off <<= 1) {
                pa += __shfl_xor_sync(0xffffffffu, pa, off);
                pb += __shfl_xor_sync(0xffffffffu, pb, off);
            }
            const float exa = 1.f + ex2f(fmaf(l2sp(pa), sa_a, sbL_a));
            const float exb = 1.f + ex2f(fmaf(l2sp(pb), sa_b, sbL_b));
            if ((lane & 15) == 0) {
                atomicAdd(&g_denom[ni * HEADS + ha], exa);
                atomicAdd(&g_denom[ni * HEADS + hb], exb);
            }
            red4(&g_num[(size_t)ni * C + lane * 4],
                 make_float4(Lja.x * exa, Lja.y * exa, Lja.z * exa, Lja.w * exa));
            red4(&g_num[(size_t)ni * C + 128 + lane * 4],
                 make_float4(Ljb.x * exb, Ljb.y * exb, Ljb.z * exb, Ljb.w * exb));
        }
        cur ^= 1;
    }
}

// out[n] = bias + 0.25*ln2 * sum_h num[n,h]/denom[n,h]
__global__ void k_final(const float* __restrict__ bias, float* __restrict__ out) {
    int i = blockIdx.x * blockDim.x + threadIdx.x;   // N_NODES*16 quads
    if (i >= N_NODES * 16) return;
    int n = i >> 4, q = i & 15;
    float inv[HEADS];
#pragma unroll
    for (int hh = 0; hh < HEADS; hh++) {
        float dn = g_denom[n * HEADS + hh];
        inv[hh] = (dn > 0.f) ? (0.25f * LN2) / dn : 0.f;
    }
    float4 acc = make_float4(0.f, 0.f, 0.f, 0.f);
#pragma unroll
    for (int hh = 0; hh < HEADS; hh++) {
        float4 v = *(const float4*)&g_num[n * C + hh * DIM + q * 4];
        acc.x += v.x * inv[hh]; acc.y += v.y * inv[hh];
        acc.z += v.z * inv[hh]; acc.w += v.w * inv[hh];
    }
    float4 b = *(const float4*)&bias[q * 4];
    acc.x += b.x; acc.y += b.y; acc.z += b.z; acc.w += b.w;
    *(float4*)&out[n * DIM + q * 4] = acc;
}

extern "C" void kernel_launch(void* const* d_in, const int* in_sizes, int n_in,
                              void* d_out, int out_size) {
    const float* x         = (const float*)d_in[0];
    const float* edge_attr = (const float*)d_in[1];
    const float* W         = (const float*)d_in[2];
    const float* att       = (const float*)d_in[3];
    const float* bias      = (const float*)d_in[4];
    const float* bn_g      = (const float*)d_in[5];
    const float* bn_b      = (const float*)d_in[6];
    const float* bn_m      = (const float*)d_in[7];
    const float* bn_v      = (const float*)d_in[8];
    const int*   ei        = (const int*)d_in[9];
    float* out = (float*)d_out;

    cudaFuncSetAttribute(k_edge, cudaFuncAttributeMaxDynamicSharedMemorySize, SMEM_TOTAL);

    k_init<<<(N_NODES * C / 4 + 255) / 256, 256>>>();
    k_P<<<592, 256>>>(x, W);
    k_edge<<<592, 256, SMEM_TOTAL>>>(edge_attr, W, att, bn_g, bn_b, bn_m, bn_v, ei);
    k_final<<<(N_NODES * 16 + 255) / 256, 256>>>(bias, out);
}

// round 17
// speedup vs baseline: 2.1721x; 1.1389x over previous
#include <cuda_runtime.h>
#include <math.h>

#define N_NODES 25000
#define N_EDGES 250000
#define DIM 64
#define HEADS 4
#define C 256            // HEADS*DIM
#define EB 16            // edges per tile (mma m16)
#define NPT 16           // nodes per k_P tile
#define SQH 132          // sq row stride (uints, bf16 pairs): conflict-free
#define SEAS 36          // sea row stride (uints, bf16 pairs): conflict-free frag loads
#define LOG2E 1.4426950408889634f
#define LN2   0.6931471805599453f

// k_edge dynamic smem partition (bytes)
#define SB_BYTES   32768                          // 4096 x uint2 (bf16-pair B frags, k16 layout)
#define SEA_OFF    SB_BYTES                       // [2][EB][SEAS] unsigned = 4608
#define SQ_OFF     (SEA_OFF + 4608)               // [2][EB][SQH] unsigned = 16896
#define SII_OFF    (SQ_OFF + 16896)               // [2][EB] int = 128
#define SJJ_OFF    (SII_OFF + 128)                // [2][EB] int = 128
#define SBN_OFF    (SJJ_OFF + 128)                // [2][HEADS] float = 32
#define SMEM_TOTAL (SBN_OFF + 32)                 // 54560 B -> 4 CTAs/SM

// Scratch
__device__ unsigned g_Ph[N_NODES * 128];                 // bf16-pair (x @ W_top)*log2e (12.8MB)
__device__ __align__(16) float g_num[N_NODES * C];       // unnormalized aggregation (log2-domain)
__device__ float g_denom[N_NODES * HEADS];

__device__ __forceinline__ float ex2f(float x) {
    float r; asm("ex2.approx.f32 %0, %1;" : "=f"(r) : "f"(x)); return r;
}
__device__ __forceinline__ float lg2f(float x) {
    float r; asm("lg2.approx.f32 %0, %1;" : "=f"(r) : "f"(x)); return r;
}
// log2-domain softplus: arg pre-scaled by log2e; returns softplus(arg/log2e)/ln2
__device__ __forceinline__ float l2sp(float x) { return lg2f(1.f + ex2f(x)); }

// pack bf16: lo = first, hi = second
__device__ __forceinline__ unsigned pk2bf16(float lo, float hi) {
    unsigned r;
    asm("{.reg .b16 l, h; cvt.rn.bf16.f32 l, %1; cvt.rn.bf16.f32 h, %2; mov.b32 %0, {l, h};}"
        : "=r"(r) : "f"(lo), "f"(hi));
    return r;
}
__device__ __forceinline__ float bf_lo(unsigned u) { return __uint_as_float(u << 16); }
__device__ __forceinline__ float bf_hi(unsigned u) { return __uint_as_float(u & 0xffff0000u); }
__device__ __forceinline__ float4 bfx4(uint2 u) {
    return make_float4(bf_lo(u.x), bf_hi(u.x), bf_lo(u.y), bf_hi(u.y));
}

// m16n8k16 bf16 MMA: D += A x B
__device__ __forceinline__ void mma_bf16(float* d, const unsigned* a, unsigned b0, unsigned b1) {
    asm("mma.sync.aligned.m16n8k16.row.col.f32.bf16.bf16.f32 "
        "{%0,%1,%2,%3}, {%4,%5,%6,%7}, {%8,%9}, {%0,%1,%2,%3};"
        : "+f"(d[0]), "+f"(d[1]), "+f"(d[2]), "+f"(d[3])
        : "r"(a[0]), "r"(a[1]), "r"(a[2]), "r"(a[3]), "r"(b0), "r"(b1));
}
__device__ __forceinline__ float4 l2sp4(float4 p, float4 q) {
    return make_float4(l2sp(p.x + q.x), l2sp(p.y + q.y), l2sp(p.z + q.z), l2sp(p.w + q.w));
}
__device__ __forceinline__ float dot4acc(float acc, float4 o, float4 c) {
    return fmaf(o.x, c.x, fmaf(o.y, c.y, fmaf(o.z, c.z, fmaf(o.w, c.w, acc))));
}
__device__ __forceinline__ void red4(float* p, float4 v) {
    asm volatile("red.global.add.v4.f32 [%0], {%1, %2, %3, %4};"
                 :: "l"(p), "f"(v.x), "f"(v.y), "f"(v.z), "f"(v.w) : "memory");
}

// P' = (x @ W_top)*log2e via bf16 MMA, written as bf16 pairs. Inits fused.
__global__ void __launch_bounds__(256, 2) k_P(const float* __restrict__ x,
                                              const float* __restrict__ W) {
    const int t = threadIdx.x;
    const int w = t >> 5, lane = t & 31;
    const int g = lane >> 2, tg = lane & 3;

    // fused zero-init (grid-stride; disjoint from g_Ph writes)
    for (int i = blockIdx.x * 256 + t; i < N_NODES * C / 4; i += gridDim.x * 256)
        ((float4*)g_num)[i] = make_float4(0.f, 0.f, 0.f, 0.f);
    for (int i = blockIdx.x * 256 + t; i < N_NODES * HEADS; i += gridDim.x * 256)
        g_denom[i] = 0.f;

    __shared__ uint2    sB2[4096];        // W_top bf16 frags (k16 layout), x log2e
    __shared__ unsigned sxa[NPT][SEAS];   // x rows as bf16 pairs

    // B-fill: W rows 0..63 (W_top)
#pragma unroll
    for (int it = 0; it < 16; it++) {
        const int idx = t + it * 256;
        const int chunk = idx >> 5, l = idx & 31;
        const int wv = chunk >> 4, nb = (chunk >> 2) & 3, s = chunk & 3;
        const int gg = l >> 2, tt = l & 3;
        const int n  = wv * 32 + nb * 8 + gg;
        const int k0 = s * 16 + 2 * tt;
        sB2[idx] = make_uint2(
            pk2bf16(LOG2E * W[k0 * C + n],       LOG2E * W[(k0 + 1) * C + n]),
            pk2bf16(LOG2E * W[(k0 + 8) * C + n], LOG2E * W[(k0 + 9) * C + n]));
    }
    const int e_ld = t >> 4, q4_ld = t & 15;

    for (int base = blockIdx.x * NPT; base < N_NODES; base += gridDim.x * NPT) {
        __syncthreads();   // protect previous tile's sxa reads (and 1st-iter B-fill)
        {
            const int n = base + e_ld;
            if (n < N_NODES) {
                const float4 v = *(const float4*)&x[(size_t)n * DIM + q4_ld * 4];
                *(uint2*)&sxa[e_ld][q4_ld * 2] =
                    make_uint2(pk2bf16(v.x, v.y), pk2bf16(v.z, v.w));
            }
        }
        __syncthreads();

        float D[4][4];
#pragma unroll
        for (int nb = 0; nb < 4; nb++)
#pragma unroll
            for (int r = 0; r < 4; r++) D[nb][r] = 0.f;
#pragma unroll
        for (int s = 0; s < 4; s++) {
            unsigned a[4];
            a[0] = sxa[g][s * 8 + tg];
            a[1] = sxa[g + 8][s * 8 + tg];
            a[2] = sxa[g][s * 8 + 4 + tg];
            a[3] = sxa[g + 8][s * 8 + 4 + tg];
#pragma unroll
            for (int nb = 0; nb < 4; nb++) {
                const uint2 b = sB2[(w * 16 + nb * 4 + s) * 32 + lane];
                mma_bf16(D[nb], a, b.x, b.y);
            }
        }
        const int n0 = base + g, n1 = base + g + 8;
#pragma unroll
        for (int nb = 0; nb < 4; nb++) {
            const int ci = w * 16 + nb * 4 + tg;
            if (n0 < N_NODES) g_Ph[(size_t)n0 * 128 + ci] = pk2bf16(D[nb][0], D[nb][1]);
            if (n1 < N_NODES) g_Ph[(size_t)n1 * 128 + ci] = pk2bf16(D[nb][2], D[nb][3]);
        }
    }
}

// Fused edge pass: bf16 k16 MMA -> bf16 smem redistribute -> coalesced log2 epilogue.
__global__ void __launch_bounds__(256, 4) k_edge(
    const float* __restrict__ edge_attr, const float* __restrict__ W,
    const float* __restrict__ att, const float* __restrict__ bn_g,
    const float* __restrict__ bn_b, const float* __restrict__ bn_m,
    const float* __restrict__ bn_v, const int* __restrict__ ei) {
    const int t = threadIdx.x;
    const int w = t >> 5, lane = t & 31;
    const int g = lane >> 2, tg = lane & 3;

    extern __shared__ __align__(16) char dyn[];
    uint2*    sB2  = (uint2*)dyn;                                       // [4096] k16 B frags
    unsigned (*sea)[EB][SEAS] = (unsigned(*)[EB][SEAS])(dyn + SEA_OFF); // bf16-pair A
    unsigned (*sq)[EB][SQH]   = (unsigned(*)[EB][SQH])(dyn + SQ_OFF);   // bf16-pair q
    int      (*sii)[EB]       = (int(*)[EB])(dyn + SII_OFF);
    int      (*sjj)[EB]       = (int(*)[EB])(dyn + SJJ_OFF);
    float    (*sbn)[HEADS]    = (float(*)[HEADS])(dyn + SBN_OFF);

    // Fill B fragments (k16 layout, W_bot pre-scaled by log2e)
#pragma unroll
    for (int it = 0; it < 16; it++) {
        const int idx = t + it * 256;
        const int chunk = idx >> 5, l = idx & 31;
        const int wv = chunk >> 4, nb = (chunk >> 2) & 3, s = chunk & 3;
        const int gg = l >> 2, tt = l & 3;
        const int n  = wv * 32 + nb * 8 + gg;
        const int k0 = s * 16 + 2 * tt;
        sB2[idx] = make_uint2(
            pk2bf16(LOG2E * W[(DIM + k0) * C + n],     LOG2E * W[(DIM + k0 + 1) * C + n]),
            pk2bf16(LOG2E * W[(DIM + k0 + 8) * C + n], LOG2E * W[(DIM + k0 + 9) * C + n]));
    }
    if (t < HEADS) {
        float s = bn_g[t] * rsqrtf(bn_v[t] + 1e-5f);
        sbn[0][t] = s;                               // scale: ln2*log2e = 1 folds exactly
        sbn[1][t] = (bn_b[t] - bn_m[t] * s) * LOG2E; // shift pre-scaled by log2e
    }

    // per-lane att coefficients
    const int ha = lane >> 4, hb = 2 + ha;
    const int da = (lane * 4) & 63;
    const float4 aia = *(const float4*)&att[ha * 128 + da];
    const float4 aja = *(const float4*)&att[ha * 128 + 64 + da];
    const float4 aib = *(const float4*)&att[hb * 128 + da];
    const float4 ajb = *(const float4*)&att[hb * 128 + 64 + da];

    const int* idx_i = ei;
    const int* idx_j = ei + N_EDGES;
    const int e_ld = t >> 4, q4_ld = t & 15;
    const int stride = gridDim.x * EB;

    // prologue: tile 0 -> buffer 0
    int base0 = blockIdx.x * EB;
    {
        const float4 v = *(const float4*)&edge_attr[(size_t)(base0 + e_ld) * DIM + q4_ld * 4];
        *(uint2*)&sea[0][e_ld][q4_ld * 2] =
            make_uint2(pk2bf16(v.x, v.y), pk2bf16(v.z, v.w));
        if (t < EB) sii[0][t] = idx_i[base0 + t];
        else if (t < 2 * EB) sjj[0][t - EB] = idx_j[base0 + t - EB];
    }
    __syncthreads();   // covers B-fill + sbn + tile 0

    const float sa_a = sbn[0][ha], sbL_a = sbn[1][ha];
    const float sa_b = sbn[0][hb], sbL_b = sbn[1][hb];
    const int e0 = 2 * w, e1 = 2 * w + 1;

    int cur = 0;
    for (int base = base0; base < N_EDGES; base += stride) {
        const int nbase = base + stride;
        const bool has = nbase < N_EDGES;
        float4 vnext;
        int ij_next = 0;
        if (has) {
            vnext = *(const float4*)&edge_attr[(size_t)(nbase + e_ld) * DIM + q4_ld * 4];
            if (t < EB) ij_next = idx_i[nbase + t];
            else if (t < 2 * EB) ij_next = idx_j[nbase + t - EB];
        }
        const int ni0 = sii[cur][e0], nj0 = sjj[cur][e0];
        const int ni1 = sii[cur][e1], nj1 = sjj[cur][e1];

        // ---- bf16 k16 MMA: q'[16 edges, 32 cols], 16 HMMA total ----
        float D[4][4];
#pragma unroll
        for (int nb = 0; nb < 4; nb++)
#pragma unroll
            for (int r = 0; r < 4; r++) D[nb][r] = 0.f;
#pragma unroll
        for (int s = 0; s < 4; s++) {
            unsigned a[4];
            a[0] = sea[cur][g][s * 8 + tg];
            a[1] = sea[cur][g + 8][s * 8 + tg];
            a[2] = sea[cur][g][s * 8 + 4 + tg];
            a[3] = sea[cur][g + 8][s * 8 + 4 + tg];
#pragma unroll
            for (int nb = 0; nb < 4; nb++) {
                const uint2 b = sB2[(w * 16 + nb * 4 + s) * 32 + lane];
                mma_bf16(D[nb], a, b.x, b.y);
            }
        }

        // ---- redistribute q' as bf16 pairs (conflict-free STS.32) ----
#pragma unroll
        for (int nb = 0; nb < 4; nb++) {
            const int ci = w * 16 + nb * 4 + tg;
            sq[cur][g][ci]     = pk2bf16(D[nb][0], D[nb][1]);
            sq[cur][g + 8][ci] = pk2bf16(D[nb][2], D[nb][3]);
        }

        // commit next tile into the other buffer
        if (has) {
            *(uint2*)&sea[cur ^ 1][e_ld][q4_ld * 2] =
                make_uint2(pk2bf16(vnext.x, vnext.y), pk2bf16(vnext.z, vnext.w));
            if (t < EB) sii[cur ^ 1][t] = ij_next;
            else if (t < 2 * EB) sjj[cur ^ 1][t - EB] = ij_next;
        }
        __syncthreads();   // single barrier per tile

        // ---- coalesced log2-domain epilogue: warp w owns edges e0, e1 ----
        const int l2i = lane * 2;
#pragma unroll
        for (int sub = 0; sub < 2; sub++) {
            const int e  = sub ? e1 : e0;
            const int ni = sub ? ni1 : ni0;
            const int nj = sub ? nj1 : nj0;

            const float4 qa = bfx4(*(const uint2*)&sq[cur][e][l2i]);
            const float4 qb = bfx4(*(const uint2*)&sq[cur][e][64 + l2i]);
            const float4 pia = bfx4(*(const uint2*)&g_Ph[(size_t)ni * 128 + l2i]);
            const float4 pib = bfx4(*(const uint2*)&g_Ph[(size_t)ni * 128 + 64 + l2i]);
            const float4 pja = bfx4(*(const uint2*)&g_Ph[(size_t)nj * 128 + l2i]);
            const float4 pjb = bfx4(*(const uint2*)&g_Ph[(size_t)nj * 128 + 64 + l2i]);

            const float4 Lia = l2sp4(pia, qa), Lja = l2sp4(pja, qa);
            const float4 Lib = l2sp4(pib, qb), Ljb = l2sp4(pjb, qb);

            float pa = dot4acc(dot4acc(0.f, Lia, aia), Lja, aja);
            float pb = dot4acc(dot4acc(0.f, Lib, aib), Ljb, ajb);
#pragma unroll
            for (int off = 1; off < 16; off <<= 1) {
                pa += __shfl_xor_sync(0xffffffffu, pa, off);
                pb += __shfl_xor_sync(0xffffffffu, pb, off);
            }
            const float exa = 1.f + ex2f(fmaf(l2sp(pa), sa_a, sbL_a));
            const float exb = 1.f + ex2f(fmaf(l2sp(pb), sa_b, sbL_b));
            if ((lane & 15) == 0) {
                atomicAdd(&g_denom[ni * HEADS + ha], exa);
                atomicAdd(&g_denom[ni * HEADS + hb], exb);
            }
            red4(&g_num[(size_t)ni * C + lane * 4],
                 make_float4(Lja.x * exa, Lja.y * exa, Lja.z * exa, Lja.w * exa));
            red4(&g_num[(size_t)ni * C + 128 + lane * 4],
                 make_float4(Ljb.x * exb, Ljb.y * exb, Ljb.z * exb, Ljb.w * exb));
        }
        cur ^= 1;
    }
}

// out[n] = bias + 0.25*ln2 * sum_h num[n,h]/denom[n,h]
__global__ void k_final(const float* __restrict__ bias, float* __restrict__ out) {
    int i = blockIdx.x * blockDim.x + threadIdx.x;   // N_NODES*16 quads
    if (i >= N_NODES * 16) return;
    int n = i >> 4, q = i & 15;
    float inv[HEADS];
#pragma unroll
    for (int hh = 0; hh < HEADS; hh++) {
        float dn = g_denom[n * HEADS + hh];
        inv[hh] = (dn > 0.f) ? (0.25f * LN2) / dn : 0.f;
    }
    float4 acc = make_float4(0.f, 0.f, 0.f, 0.f);
#pragma unroll
    for (int hh = 0; hh < HEADS; hh++) {
        float4 v = *(const float4*)&g_num[n * C + hh * DIM + q * 4];
        acc.x += v.x * inv[hh]; acc.y += v.y * inv[hh];
        acc.z += v.z * inv[hh]; acc.w += v.w * inv[hh];
    }
    float4 b = *(const float4*)&bias[q * 4];
    acc.x += b.x; acc.y += b.y; acc.z += b.z; acc.w += b.w;
    *(float4*)&out[n * DIM + q * 4] = acc;
}

extern "C" void kernel_launch(void* const* d_in, const int* in_sizes, int n_in,
                              void* d_out, int out_size) {
    const float* x         = (const float*)d_in[0];
    const float* edge_attr = (const float*)d_in[1];
    const float* W         = (const float*)d_in[2];
    const float* att       = (const float*)d_in[3];
    const float* bias      = (const float*)d_in[4];
    const float* bn_g      = (const float*)d_in[5];
    const float* bn_b      = (const float*)d_in[6];
    const float* bn_m      = (const float*)d_in[7];
    const float* bn_v      = (const float*)d_in[8];
    const int*   ei        = (const int*)d_in[9];
    float* out = (float*)d_out;

    cudaFuncSetAttribute(k_edge, cudaFuncAttributeMaxDynamicSharedMemorySize, SMEM_TOTAL);

    k_P<<<592, 256>>>(x, W);
    k_edge<<<592, 256, SMEM_TOTAL>>>(edge_attr, W, att, bn_g, bn_b, bn_m, bn_v, ei);
    k_final<<<(N_NODES * 16 + 255) / 256, 256>>>(bias, out);
}